// round 1
// baseline (speedup 1.0000x reference)
#include <cuda_runtime.h>
#include <math.h>

#define BGR 64
#define NPG0 2048
#define EDG  524288
#define H 128
#define K1 1639
#define K2 1312
#define K3 1050
#define ACT 124
#define NMAX 131072

// ---------------- scratch (device globals; no allocation allowed) ----------------
__device__ float g_buf0[(size_t)NMAX * H];
__device__ float g_buf1[(size_t)NMAX * H];
__device__ float g_deg[NMAX];          // becomes dis = rsqrt(deg)
__device__ int   g_cnt[NMAX];
__device__ int   g_rowstart[NMAX];
__device__ int   g_esrc[EDG];
__device__ int   g_edst[EDG];
__device__ int   g_evalid[EDG];
__device__ int   g_eadj[EDG];          // src ids bucketed by dst
__device__ float g_score[NMAX];
__device__ int   g_newpos[NMAX];
__device__ int   g_oldidx[NMAX];
__device__ int   g_bsums[512];
__device__ float g_pnorm[4];
__device__ float g_accz[BGR * 256];
__device__ float g_z1[BGR * 128];
__device__ float g_z2[BGR * 64];

// ---------------- tiny utility kernels ----------------
__global__ void pnorm_kernel(const float* p1, const float* p2, const float* p3, float* out) {
    __shared__ float red[128];
    const float* ps[3] = {p1, p2, p3};
    int t = threadIdx.x;
    for (int l = 0; l < 3; l++) {
        red[t] = ps[l][t] * ps[l][t];
        __syncthreads();
        for (int off = 64; off; off >>= 1) {
            if (t < off) red[t] += red[t + off];
            __syncthreads();
        }
        if (t == 0) out[l] = sqrtf(red[0]);
        __syncthreads();
    }
}

__global__ void edge_init(const int* __restrict__ src, const int* __restrict__ dst,
                          int* __restrict__ esrc, int* __restrict__ edst, int* __restrict__ evalid) {
    int e = blockIdx.x * blockDim.x + threadIdx.x;
    esrc[e] = src[e];
    edst[e] = dst[e];
    evalid[e] = 1;
}

__global__ void node_init(float* __restrict__ deg, int* __restrict__ cnt, int n) {
    int i = blockIdx.x * blockDim.x + threadIdx.x;
    if (i < n) { deg[i] = 1.0f; cnt[i] = 0; }
}

__global__ void edge_count(const int* __restrict__ edst, const int* __restrict__ evalid,
                           float* __restrict__ deg, int* __restrict__ cnt) {
    int e = blockIdx.x * blockDim.x + threadIdx.x;
    if (evalid[e]) {
        atomicAdd(&deg[edst[e]], 1.0f);
        atomicAdd(&cnt[edst[e]], 1);
    }
}

__global__ void dis_kernel(float* __restrict__ deg, int n) {
    int i = blockIdx.x * blockDim.x + threadIdx.x;
    if (i < n) deg[i] = rsqrtf(deg[i]);
}

// ---------------- exclusive scans for CSR rowstart ----------------
__global__ void scan_block(const int* __restrict__ cnt, int* __restrict__ rowstart,
                           int* __restrict__ bsums, int n) {
    __shared__ int s[512];
    int t = threadIdx.x;
    int base = blockIdx.x * 512;
    int i = base + t;
    s[t] = (i < n) ? cnt[i] : 0;
    int offset = 1;
    for (int d = 256; d > 0; d >>= 1) {
        __syncthreads();
        if (t < d) {
            int ai = offset * (2 * t + 1) - 1;
            int bi = offset * (2 * t + 2) - 1;
            s[bi] += s[ai];
        }
        offset <<= 1;
    }
    __syncthreads();
    if (t == 0) { bsums[blockIdx.x] = s[511]; s[511] = 0; }
    for (int d = 1; d < 512; d <<= 1) {
        offset >>= 1;
        __syncthreads();
        if (t < d) {
            int ai = offset * (2 * t + 1) - 1;
            int bi = offset * (2 * t + 2) - 1;
            int tmp = s[ai]; s[ai] = s[bi]; s[bi] += tmp;
        }
    }
    __syncthreads();
    if (i < n) rowstart[i] = s[t];
}

__global__ void scan_sums(int* __restrict__ bsums, int nb) {
    __shared__ int s[512];
    int t = threadIdx.x;
    s[t] = (t < nb) ? bsums[t] : 0;
    int offset = 1;
    for (int d = 256; d > 0; d >>= 1) {
        __syncthreads();
        if (t < d) {
            int ai = offset * (2 * t + 1) - 1;
            int bi = offset * (2 * t + 2) - 1;
            s[bi] += s[ai];
        }
        offset <<= 1;
    }
    __syncthreads();
    if (t == 0) s[511] = 0;
    for (int d = 1; d < 512; d <<= 1) {
        offset >>= 1;
        __syncthreads();
        if (t < d) {
            int ai = offset * (2 * t + 1) - 1;
            int bi = offset * (2 * t + 2) - 1;
            int tmp = s[ai]; s[ai] = s[bi]; s[bi] += tmp;
        }
    }
    __syncthreads();
    if (t < nb) bsums[t] = s[t];
}

__global__ void scan_add(int* __restrict__ rowstart, const int* __restrict__ bsums, int n) {
    int i = blockIdx.x * blockDim.x + threadIdx.x;
    if (i < n) rowstart[i] += bsums[i >> 9];
}

__global__ void edge_fill(const int* __restrict__ esrc, const int* __restrict__ edst,
                          const int* __restrict__ evalid, int* __restrict__ rowstart,
                          int* __restrict__ eadj) {
    int e = blockIdx.x * blockDim.x + threadIdx.x;
    if (evalid[e]) {
        int pos = atomicAdd(&rowstart[edst[e]], 1);
        eadj[pos] = esrc[e];
    }
}

// ---------------- matmuls ----------------
__global__ void mm_fin4(const float* __restrict__ X, const float* __restrict__ W,
                        float* __restrict__ Y, int n) {
    int idx = blockIdx.x * blockDim.x + threadIdx.x;
    if (idx >= n * H) return;
    int i = idx >> 7, f = idx & 127;
    const float* xr = X + i * 4;
    float a = xr[0] * W[f] + xr[1] * W[128 + f] + xr[2] * W[256 + f] + xr[3] * W[384 + f];
    Y[idx] = a;
}

// Y[n,128] = A[n,128] @ W[128,128]; block tile 64x128, BK=16, 256 threads, 4x8 per thread
__global__ __launch_bounds__(256) void sgemm128(const float* __restrict__ A,
                                                const float* __restrict__ W,
                                                float* __restrict__ Y, int n) {
    __shared__ float As[16][64];
    __shared__ float Bs[16][128];
    int bm = blockIdx.x * 64;
    int tid = threadIdx.x;
    int tx = tid & 15, ty = tid >> 4;
    float acc[4][8];
#pragma unroll
    for (int m = 0; m < 4; m++)
#pragma unroll
        for (int j = 0; j < 8; j++) acc[m][j] = 0.f;

    for (int k0 = 0; k0 < 128; k0 += 16) {
        {
            int r = tid >> 2;
            int c4 = (tid & 3) * 4;
            int row = bm + r;
            float4 v = make_float4(0.f, 0.f, 0.f, 0.f);
            if (row < n) v = *(const float4*)&A[(size_t)row * 128 + k0 + c4];
            As[c4 + 0][r] = v.x; As[c4 + 1][r] = v.y; As[c4 + 2][r] = v.z; As[c4 + 3][r] = v.w;
        }
#pragma unroll
        for (int i = 0; i < 2; i++) {
            int idx = tid + i * 256;       // float4 index 0..511
            int r = idx >> 5;
            int c = (idx & 31) * 4;
            *(float4*)&Bs[r][c] = *(const float4*)&W[(size_t)(k0 + r) * 128 + c];
        }
        __syncthreads();
#pragma unroll
        for (int kk = 0; kk < 16; kk++) {
            float a[4], b[8];
#pragma unroll
            for (int m = 0; m < 4; m++) a[m] = As[kk][ty * 4 + m];
#pragma unroll
            for (int j = 0; j < 8; j++) b[j] = Bs[kk][tx * 8 + j];
#pragma unroll
            for (int m = 0; m < 4; m++)
#pragma unroll
                for (int j = 0; j < 8; j++) acc[m][j] += a[m] * b[j];
        }
        __syncthreads();
    }
#pragma unroll
    for (int m = 0; m < 4; m++) {
        int row = bm + ty * 4 + m;
        if (row < n) {
            *(float4*)&Y[(size_t)row * 128 + tx * 8]     = make_float4(acc[m][0], acc[m][1], acc[m][2], acc[m][3]);
            *(float4*)&Y[(size_t)row * 128 + tx * 8 + 4] = make_float4(acc[m][4], acc[m][5], acc[m][6], acc[m][7]);
        }
    }
}

// ---------------- GCN aggregation (gather over CSR) + relu + score ----------------
__global__ void gcn_gather(const float* __restrict__ H2, const int* __restrict__ eadj,
                           const int* __restrict__ rowend, const int* __restrict__ cnt,
                           const float* __restrict__ dis, const float* __restrict__ bias,
                           const float* __restrict__ p, const float* __restrict__ pnorm, int lvl,
                           float* __restrict__ Out, float* __restrict__ score) {
    int i = blockIdx.x, f = threadIdx.x;
    float di = dis[i];
    float acc = H2[(size_t)i * H + f] * di * di + bias[f];
    int c = cnt[i];
    int st = rowend[i] - c;
    for (int e = 0; e < c; e++) {
        int s = eadj[st + e];
        acc += H2[(size_t)s * H + f] * (dis[s] * di);
    }
    float v = fmaxf(acc, 0.f);
    Out[(size_t)i * H + f] = v;
    __shared__ float red[128];
    red[f] = v * p[f];
    __syncthreads();
    for (int off = 64; off; off >>= 1) {
        if (f < off) red[f] += red[f + off];
        __syncthreads();
    }
    if (f == 0) score[i] = tanhf(red[0] / pnorm[lvl]);
}

// ---------------- top-k per graph (bitonic sort + scans) ----------------
__device__ __forceinline__ void scan2048(int* s, int t) {
    int offset = 1;
    for (int d = 1024; d > 0; d >>= 1) {
        __syncthreads();
        if (t < d) {
            int ai = offset * (2 * t + 1) - 1;
            int bi = offset * (2 * t + 2) - 1;
            s[bi] += s[ai];
        }
        offset <<= 1;
    }
    __syncthreads();
    if (t == 0) s[2047] = 0;
    for (int d = 1; d < 2048; d <<= 1) {
        offset >>= 1;
        __syncthreads();
        if (t < d) {
            int ai = offset * (2 * t + 1) - 1;
            int bi = offset * (2 * t + 2) - 1;
            int tmp = s[ai]; s[ai] = s[bi]; s[bi] += tmp;
        }
    }
    __syncthreads();
}

__global__ __launch_bounds__(1024) void topk_kernel(const float* __restrict__ score, int n, int kk,
                                                    int* __restrict__ newpos, int* __restrict__ oldidx) {
    __shared__ float sc[2048];
    __shared__ float sv[2048];
    __shared__ int   si[2048];
    __shared__ int   sh_cG;
    int g = blockIdx.x;
    int t = threadIdx.x;
    for (int i = t; i < 2048; i += 1024) {
        float v = (i < n) ? score[g * n + i] : -1e30f;
        sc[i] = v;
        sv[i] = v;
    }
    __syncthreads();
    // bitonic sort ascending over 2048
    for (int k2 = 2; k2 <= 2048; k2 <<= 1) {
        for (int j = k2 >> 1; j > 0; j >>= 1) {
            for (int i = t; i < 2048; i += 1024) {
                int ixj = i ^ j;
                if (ixj > i) {
                    bool up = ((i & k2) == 0);
                    float a = sv[i], b = sv[ixj];
                    if ((a > b) == up) { sv[i] = b; sv[ixj] = a; }
                }
            }
            __syncthreads();
        }
    }
    float thr = sv[2048 - kk];   // k-th largest
    if (t == 0) sh_cG = 0;
    __syncthreads();
    int loc = 0;
    for (int i = t; i < 2048; i += 1024) if (sc[i] > thr) loc++;
    if (loc) atomicAdd(&sh_cG, loc);
    __syncthreads();
    int needEq = kk - sh_cG;
    // rank among equal-to-threshold by index (matches JAX tie-break)
    for (int i = t; i < 2048; i += 1024) si[i] = (sc[i] == thr) ? 1 : 0;
    scan2048(si, t);
    int keep[2];
#pragma unroll
    for (int u = 0; u < 2; u++) {
        int i = t + u * 1024;
        float v = sc[i];
        keep[u] = (v > thr) || (v == thr && si[i] < needEq);
    }
    __syncthreads();
#pragma unroll
    for (int u = 0; u < 2; u++) si[t + u * 1024] = keep[u];
    scan2048(si, t);
#pragma unroll
    for (int u = 0; u < 2; u++) {
        int i = t + u * 1024;
        if (i < n) {
            if (keep[u]) {
                int pos = g * kk + si[i];
                newpos[g * n + i] = pos;
                oldidx[pos] = g * n + i;
            } else {
                newpos[g * n + i] = -1;
            }
        }
    }
}

__global__ void pool_copy(const float* __restrict__ Hc, const float* __restrict__ score,
                          const int* __restrict__ oldidx, float* __restrict__ Xn) {
    int p = blockIdx.x, f = threadIdx.x;
    int o = oldidx[p];
    Xn[(size_t)p * H + f] = Hc[(size_t)o * H + f] * score[o];
}

__global__ void readout_kernel(const float* __restrict__ Xn, int kk,
                               float* __restrict__ accz, int first) {
    int g = blockIdx.x, f = threadIdx.x;
    const float* base = Xn + (size_t)g * kk * H + f;
    float mx = -1e30f, sm = 0.f;
    for (int j = 0; j < kk; j++) {
        float v = base[(size_t)j * H];
        mx = fmaxf(mx, v);
        sm += v;
    }
    float mean = sm / (float)kk;
    if (first) {
        accz[g * 256 + f] = mx;
        accz[g * 256 + 128 + f] = mean;
    } else {
        accz[g * 256 + f] += mx;
        accz[g * 256 + 128 + f] += mean;
    }
}

__global__ void remap_edges(int* __restrict__ esrc, int* __restrict__ edst,
                            int* __restrict__ evalid, const int* __restrict__ newpos) {
    int e = blockIdx.x * blockDim.x + threadIdx.x;
    if (evalid[e]) {
        int s = newpos[esrc[e]];
        int d = newpos[edst[e]];
        if (s >= 0 && d >= 0) { esrc[e] = s; edst[e] = d; }
        else { esrc[e] = 0; edst[e] = 0; evalid[e] = 0; }
    }
}

// ---------------- MLP head ----------------
__global__ void mlp1_kernel(const float* __restrict__ z, const float* __restrict__ W,
                            const float* __restrict__ b, float* __restrict__ out) {
    int g = blockIdx.x, j = threadIdx.x;  // 128 threads
    __shared__ float zr[256];
    zr[j] = z[g * 256 + j];
    zr[128 + j] = z[g * 256 + 128 + j];
    __syncthreads();
    float a = b[j];
    for (int k = 0; k < 256; k++) a += zr[k] * W[k * 128 + j];
    out[g * 128 + j] = fmaxf(a, 0.f);
}

__global__ void mlp2_kernel(const float* __restrict__ z, const float* __restrict__ W,
                            const float* __restrict__ b, float* __restrict__ out) {
    int g = blockIdx.x, j = threadIdx.x;  // 64 threads
    __shared__ float zr[128];
    zr[j] = z[g * 128 + j];
    zr[64 + j] = z[g * 128 + 64 + j];
    __syncthreads();
    float a = b[j];
    for (int k = 0; k < 128; k++) a += zr[k] * W[k * 64 + j];
    out[g * 64 + j] = fmaxf(a, 0.f);
}

__global__ void mlp3_kernel(const float* __restrict__ z, const float* __restrict__ W,
                            const float* __restrict__ b, float* __restrict__ out) {
    int g = blockIdx.x, j = threadIdx.x;  // 124 threads
    __shared__ float zr[64];
    if (j < 64) zr[j] = z[g * 64 + j];
    __syncthreads();
    float a = b[j];
    for (int k = 0; k < 64; k++) a += zr[k] * W[k * ACT + j];
    out[g * ACT + j] = 1.f / (1.f + expf(-a));
}

// ---------------- host orchestration ----------------
extern "C" void kernel_launch(void* const* d_in, const int* in_sizes, int n_in,
                              void* d_out, int out_size) {
    const float* x   = (const float*)d_in[0];
    const int* src   = (const int*)d_in[1];
    const int* dst   = (const int*)d_in[2];
    const float* W1  = (const float*)d_in[3];
    const float* b1  = (const float*)d_in[4];
    const float* W2  = (const float*)d_in[5];
    const float* b2  = (const float*)d_in[6];
    const float* W3  = (const float*)d_in[7];
    const float* b3  = (const float*)d_in[8];
    const float* p1  = (const float*)d_in[9];
    const float* p2  = (const float*)d_in[10];
    const float* p3  = (const float*)d_in[11];
    const float* lw1 = (const float*)d_in[12];
    const float* lb1 = (const float*)d_in[13];
    const float* lw2 = (const float*)d_in[14];
    const float* lb2 = (const float*)d_in[15];
    const float* lw3 = (const float*)d_in[16];
    const float* lb3 = (const float*)d_in[17];
    float* out = (float*)d_out;

    float *buf0, *buf1, *deg, *score, *pnorm, *accz, *z1, *z2;
    int *cnt, *rowstart, *esrc, *edst, *evalid, *eadj, *newpos, *oldidx, *bsums;
    cudaGetSymbolAddress((void**)&buf0, g_buf0);
    cudaGetSymbolAddress((void**)&buf1, g_buf1);
    cudaGetSymbolAddress((void**)&deg, g_deg);
    cudaGetSymbolAddress((void**)&score, g_score);
    cudaGetSymbolAddress((void**)&pnorm, g_pnorm);
    cudaGetSymbolAddress((void**)&accz, g_accz);
    cudaGetSymbolAddress((void**)&z1, g_z1);
    cudaGetSymbolAddress((void**)&z2, g_z2);
    cudaGetSymbolAddress((void**)&cnt, g_cnt);
    cudaGetSymbolAddress((void**)&rowstart, g_rowstart);
    cudaGetSymbolAddress((void**)&esrc, g_esrc);
    cudaGetSymbolAddress((void**)&edst, g_edst);
    cudaGetSymbolAddress((void**)&evalid, g_evalid);
    cudaGetSymbolAddress((void**)&eadj, g_eadj);
    cudaGetSymbolAddress((void**)&newpos, g_newpos);
    cudaGetSymbolAddress((void**)&oldidx, g_oldidx);
    cudaGetSymbolAddress((void**)&bsums, g_bsums);

    const int npg_[3] = {2048, 1639, 1312};
    const int kk_[3]  = {K1, K2, K3};
    const int nn[4]   = {131072, 64 * K1, 64 * K2, 64 * K3};
    const float* Ws[3] = {W1, W2, W3};
    const float* bs[3] = {b1, b2, b3};
    const float* ps[3] = {p1, p2, p3};

    pnorm_kernel<<<1, 128>>>(p1, p2, p3, pnorm);
    edge_init<<<EDG / 256, 256>>>(src, dst, esrc, edst, evalid);

    const float* prev_pool = nullptr;
    for (int l = 0; l < 3; l++) {
        int n = nn[l], k = kk_[l], nk = nn[l + 1], npg = npg_[l];
        float* mm = (l & 1) ? buf1 : buf0;
        float* gt = (l & 1) ? buf0 : buf1;

        if (l == 0)
            mm_fin4<<<(n * H + 255) / 256, 256>>>(x, W1, mm, n);
        else
            sgemm128<<<(n + 63) / 64, 256>>>(prev_pool, Ws[l], mm, n);

        node_init<<<(n + 255) / 256, 256>>>(deg, cnt, n);
        edge_count<<<EDG / 256, 256>>>(edst, evalid, deg, cnt);
        dis_kernel<<<(n + 255) / 256, 256>>>(deg, n);

        int nb = (n + 511) / 512;
        scan_block<<<nb, 512>>>(cnt, rowstart, bsums, n);
        scan_sums<<<1, 512>>>(bsums, nb);
        scan_add<<<(n + 255) / 256, 256>>>(rowstart, bsums, n);
        edge_fill<<<EDG / 256, 256>>>(esrc, edst, evalid, rowstart, eadj);

        gcn_gather<<<n, 128>>>(mm, eadj, rowstart, cnt, deg, bs[l], ps[l], pnorm, l, gt, score);

        topk_kernel<<<BGR, 1024>>>(score, npg, k, newpos, oldidx);
        pool_copy<<<nk, 128>>>(gt, score, oldidx, mm);
        readout_kernel<<<BGR, 128>>>(mm, k, accz, (l == 0) ? 1 : 0);
        if (l < 2) remap_edges<<<EDG / 256, 256>>>(esrc, edst, evalid, newpos);
        prev_pool = mm;
    }

    mlp1_kernel<<<BGR, 128>>>(accz, lw1, lb1, z1);
    mlp2_kernel<<<BGR, 64>>>(z1, lw2, lb2, z2);
    mlp3_kernel<<<BGR, 124>>>(z2, lw3, lb3, out);
}

// round 2
// speedup vs baseline: 1.6158x; 1.6158x over previous
#include <cuda_runtime.h>
#include <math.h>
#include <stdint.h>

#define BGR 64
#define EDG  524288
#define H 128
#define K1 1639
#define K2 1312
#define K3 1050
#define ACT 124
#define NMAX 131072

// ---------------- scratch ----------------
__device__ float g_buf0[(size_t)NMAX * H];
__device__ float g_buf1[(size_t)NMAX * H];
__device__ int   g_cnt[NMAX];
__device__ int   g_rowstart[NMAX];
__device__ int   g_esrc[EDG];
__device__ int   g_edst[EDG];
__device__ int   g_evalid[EDG];
__device__ int   g_eadj[EDG];
__device__ float g_score[NMAX];
__device__ int   g_newpos[NMAX];
__device__ int   g_oldidx[NMAX];
__device__ int   g_bsums[512];
__device__ float g_pnorm[4];
__device__ float g_accz[BGR * 256];
__device__ float g_pmax[BGR * 13 * H];
__device__ float g_psum[BGR * 13 * H];

// ---------------- tiny utility kernels ----------------
__global__ void pnorm_kernel(const float* p1, const float* p2, const float* p3, float* out) {
    __shared__ float red[128];
    const float* ps[3] = {p1, p2, p3};
    int t = threadIdx.x;
    for (int l = 0; l < 3; l++) {
        red[t] = ps[l][t] * ps[l][t];
        __syncthreads();
        for (int off = 64; off; off >>= 1) {
            if (t < off) red[t] += red[t + off];
            __syncthreads();
        }
        if (t == 0) out[l] = sqrtf(red[0]);
        __syncthreads();
    }
}

// copy edges + count degree (cnt pre-zeroed by memset)
__global__ void edge_init_count(const int* __restrict__ src, const int* __restrict__ dst,
                                int* __restrict__ esrc, int* __restrict__ edst,
                                int* __restrict__ evalid, int* __restrict__ cnt) {
    int e = blockIdx.x * blockDim.x + threadIdx.x;
    int s = src[e], d = dst[e];
    esrc[e] = s;
    edst[e] = d;
    evalid[e] = 1;
    atomicAdd(&cnt[d], 1);
}

// remap edges to new node ids + count degrees for next level (cnt pre-zeroed)
__global__ void remap_count(int* __restrict__ esrc, int* __restrict__ edst,
                            int* __restrict__ evalid, const int* __restrict__ newpos,
                            int* __restrict__ cnt) {
    int e = blockIdx.x * blockDim.x + threadIdx.x;
    if (evalid[e]) {
        int s = newpos[esrc[e]];
        int d = newpos[edst[e]];
        if (s >= 0 && d >= 0) {
            esrc[e] = s; edst[e] = d;
            atomicAdd(&cnt[d], 1);
        } else {
            esrc[e] = 0; edst[e] = 0; evalid[e] = 0;
        }
    }
}

// ---------------- exclusive scans for CSR rowstart ----------------
__global__ void scan_block(const int* __restrict__ cnt, int* __restrict__ rowstart,
                           int* __restrict__ bsums, int n) {
    __shared__ int s[512];
    int t = threadIdx.x;
    int i = blockIdx.x * 512 + t;
    s[t] = (i < n) ? cnt[i] : 0;
    int offset = 1;
    for (int d = 256; d > 0; d >>= 1) {
        __syncthreads();
        if (t < d) {
            int ai = offset * (2 * t + 1) - 1;
            int bi = offset * (2 * t + 2) - 1;
            s[bi] += s[ai];
        }
        offset <<= 1;
    }
    __syncthreads();
    if (t == 0) { bsums[blockIdx.x] = s[511]; s[511] = 0; }
    for (int d = 1; d < 512; d <<= 1) {
        offset >>= 1;
        __syncthreads();
        if (t < d) {
            int ai = offset * (2 * t + 1) - 1;
            int bi = offset * (2 * t + 2) - 1;
            int tmp = s[ai]; s[ai] = s[bi]; s[bi] += tmp;
        }
    }
    __syncthreads();
    if (i < n) rowstart[i] = s[t];
}

__global__ void scan_sums(int* __restrict__ bsums, int nb) {
    __shared__ int s[512];
    int t = threadIdx.x;
    s[t] = (t < nb) ? bsums[t] : 0;
    int offset = 1;
    for (int d = 256; d > 0; d >>= 1) {
        __syncthreads();
        if (t < d) {
            int ai = offset * (2 * t + 1) - 1;
            int bi = offset * (2 * t + 2) - 1;
            s[bi] += s[ai];
        }
        offset <<= 1;
    }
    __syncthreads();
    if (t == 0) s[511] = 0;
    for (int d = 1; d < 512; d <<= 1) {
        offset >>= 1;
        __syncthreads();
        if (t < d) {
            int ai = offset * (2 * t + 1) - 1;
            int bi = offset * (2 * t + 2) - 1;
            int tmp = s[ai]; s[ai] = s[bi]; s[bi] += tmp;
        }
    }
    __syncthreads();
    if (t < nb) bsums[t] = s[t];
}

__global__ void scan_add(int* __restrict__ rowstart, const int* __restrict__ bsums, int n) {
    int i = blockIdx.x * blockDim.x + threadIdx.x;
    if (i < n) rowstart[i] += bsums[i >> 9];
}

__global__ void edge_fill(const int* __restrict__ esrc, const int* __restrict__ edst,
                          const int* __restrict__ evalid, int* __restrict__ rowstart,
                          int* __restrict__ eadj) {
    int e = blockIdx.x * blockDim.x + threadIdx.x;
    if (evalid[e]) {
        int pos = atomicAdd(&rowstart[edst[e]], 1);
        eadj[pos] = esrc[e];
    }
}

// ---------------- tf32 tensor-core GEMM: Y[n,128] = A[n,128] @ W[128,128] ----------------
__device__ __forceinline__ uint32_t f2tf(float f) {
    uint32_t u;
    asm("cvt.rna.tf32.f32 %0, %1;" : "=r"(u) : "f"(f));
    return u;
}

__device__ __forceinline__ void mma_tf32(float* c, uint32_t a0, uint32_t a1, uint32_t a2,
                                         uint32_t a3, uint32_t b0, uint32_t b1) {
    asm volatile(
        "mma.sync.aligned.m16n8k8.row.col.f32.tf32.tf32.f32 "
        "{%0,%1,%2,%3},{%4,%5,%6,%7},{%8,%9},{%0,%1,%2,%3};"
        : "+f"(c[0]), "+f"(c[1]), "+f"(c[2]), "+f"(c[3])
        : "r"(a0), "r"(a1), "r"(a2), "r"(a3), "r"(b0), "r"(b1));
}

__global__ __launch_bounds__(256) void sgemm_tf32(const float* __restrict__ A,
                                                  const float* __restrict__ W,
                                                  float* __restrict__ Y, int n) {
    __shared__ __align__(16) uint32_t As[2][128][12];  // padded: conflict-free a-frag loads
    __shared__ __align__(16) uint32_t Bs[2][8][136];   // padded: conflict-free b-frag loads
    int bm = blockIdx.x * 128;
    int tid = threadIdx.x;
    int lane = tid & 31, warp = tid >> 5;
    int wr = warp >> 1, wc = warp & 1;   // warp tile: rows wr*32.. , cols wc*64..

    float acc[2][8][4];
#pragma unroll
    for (int m = 0; m < 2; m++)
#pragma unroll
        for (int nt = 0; nt < 8; nt++)
#pragma unroll
            for (int q = 0; q < 4; q++) acc[m][nt][q] = 0.f;

    int arow = tid >> 1;
    int ac = (tid & 1) * 4;
    int browk = tid >> 5;            // 0..7
    int bcol = (tid & 31) * 4;

    // prologue: stage 0
    {
        float4 va = make_float4(0.f, 0.f, 0.f, 0.f);
        if (bm + arow < n) va = *(const float4*)&A[(size_t)(bm + arow) * 128 + 0 + ac];
        float4 vb = *(const float4*)&W[(size_t)browk * 128 + bcol];
        uint4 ua = make_uint4(f2tf(va.x), f2tf(va.y), f2tf(va.z), f2tf(va.w));
        uint4 ub = make_uint4(f2tf(vb.x), f2tf(vb.y), f2tf(vb.z), f2tf(vb.w));
        *(uint4*)&As[0][arow][ac] = ua;
        *(uint4*)&Bs[0][browk][bcol] = ub;
    }
    __syncthreads();

    int r0 = wr * 32 + (lane >> 2);
    int cA = lane & 3;

    for (int ks = 0; ks < 16; ks++) {
        int cur = ks & 1;
        float4 va, vb;
        if (ks < 15) {
            int k0 = (ks + 1) * 8;
            va = make_float4(0.f, 0.f, 0.f, 0.f);
            if (bm + arow < n) va = *(const float4*)&A[(size_t)(bm + arow) * 128 + k0 + ac];
            vb = *(const float4*)&W[(size_t)(k0 + browk) * 128 + bcol];
        }
        // load b fragments
        uint32_t bfr[8][2];
#pragma unroll
        for (int nt = 0; nt < 8; nt++) {
            int col = wc * 64 + nt * 8 + (lane >> 2);
            bfr[nt][0] = Bs[cur][lane & 3][col];
            bfr[nt][1] = Bs[cur][(lane & 3) + 4][col];
        }
#pragma unroll
        for (int m = 0; m < 2; m++) {
            uint32_t a0 = As[cur][r0 + m * 16][cA];
            uint32_t a1 = As[cur][r0 + m * 16 + 8][cA];
            uint32_t a2 = As[cur][r0 + m * 16][cA + 4];
            uint32_t a3 = As[cur][r0 + m * 16 + 8][cA + 4];
#pragma unroll
            for (int nt = 0; nt < 8; nt++)
                mma_tf32(acc[m][nt], a0, a1, a2, a3, bfr[nt][0], bfr[nt][1]);
        }
        if (ks < 15) {
            int nxt = cur ^ 1;
            uint4 ua = make_uint4(f2tf(va.x), f2tf(va.y), f2tf(va.z), f2tf(va.w));
            uint4 ub = make_uint4(f2tf(vb.x), f2tf(vb.y), f2tf(vb.z), f2tf(vb.w));
            *(uint4*)&As[nxt][arow][ac] = ua;
            *(uint4*)&Bs[nxt][browk][bcol] = ub;
            __syncthreads();
        }
    }

#pragma unroll
    for (int m = 0; m < 2; m++) {
#pragma unroll
        for (int nt = 0; nt < 8; nt++) {
            int row = bm + wr * 32 + m * 16 + (lane >> 2);
            int col = wc * 64 + nt * 8 + (lane & 3) * 2;
            if (row < n)
                *(float2*)&Y[(size_t)row * 128 + col] = make_float2(acc[m][nt][0], acc[m][nt][1]);
            if (row + 8 < n)
                *(float2*)&Y[(size_t)(row + 8) * 128 + col] = make_float2(acc[m][nt][2], acc[m][nt][3]);
        }
    }
}

// ---------------- level-0 fused (x@W1) + GCN gather + relu + score ----------------
__global__ void gcn_l0(const float* __restrict__ x, const float* __restrict__ W1,
                       const float* __restrict__ b1, const int* __restrict__ eadj,
                       const int* __restrict__ rowend, const int* __restrict__ cnt,
                       const float* __restrict__ p, const float* __restrict__ pnorm,
                       float* __restrict__ Out, float* __restrict__ score) {
    int i = blockIdx.x, f = threadIdx.x;
    float w0 = W1[f], w1 = W1[128 + f], w2 = W1[256 + f], w3 = W1[384 + f];
    int c = cnt[i];
    float di = rsqrtf((float)(c + 1));
    float4 xi = *(const float4*)&x[(size_t)i * 4];
    float acc = (xi.x * w0 + xi.y * w1 + xi.z * w2 + xi.w * w3) * di * di + b1[f];
    int st = rowend[i] - c;
    for (int e = 0; e < c; e++) {
        int s = eadj[st + e];
        float4 xs = *(const float4*)&x[(size_t)s * 4];
        float ds = rsqrtf((float)(cnt[s] + 1));
        acc += (xs.x * w0 + xs.y * w1 + xs.z * w2 + xs.w * w3) * (ds * di);
    }
    float v = fmaxf(acc, 0.f);
    Out[(size_t)i * H + f] = v;
    __shared__ float red[128];
    red[f] = v * p[f];
    __syncthreads();
    for (int off = 64; off; off >>= 1) {
        if (f < off) red[f] += red[f + off];
        __syncthreads();
    }
    if (f == 0) score[i] = tanhf(red[0] / pnorm[0]);
}

// ---------------- GCN aggregation (levels 1,2) + relu + score ----------------
__global__ void gcn_gather(const float* __restrict__ H2, const int* __restrict__ eadj,
                           const int* __restrict__ rowend, const int* __restrict__ cnt,
                           const float* __restrict__ bias, const float* __restrict__ p,
                           const float* __restrict__ pnorm, int lvl,
                           float* __restrict__ Out, float* __restrict__ score) {
    int i = blockIdx.x, f = threadIdx.x;
    int c = cnt[i];
    float di = rsqrtf((float)(c + 1));
    float acc = H2[(size_t)i * H + f] * di * di + bias[f];
    int st = rowend[i] - c;
    for (int e = 0; e < c; e++) {
        int s = eadj[st + e];
        float ds = rsqrtf((float)(cnt[s] + 1));
        acc += H2[(size_t)s * H + f] * (ds * di);
    }
    float v = fmaxf(acc, 0.f);
    Out[(size_t)i * H + f] = v;
    __shared__ float red[128];
    red[f] = v * p[f];
    __syncthreads();
    for (int off = 64; off; off >>= 1) {
        if (f < off) red[f] += red[f + off];
        __syncthreads();
    }
    if (f == 0) score[i] = tanhf(red[0] / pnorm[lvl]);
}

// ---------------- top-k per graph ----------------
__device__ __forceinline__ void scan2048(int* s, int t) {
    int offset = 1;
    for (int d = 1024; d > 0; d >>= 1) {
        __syncthreads();
        if (t < d) {
            int ai = offset * (2 * t + 1) - 1;
            int bi = offset * (2 * t + 2) - 1;
            s[bi] += s[ai];
        }
        offset <<= 1;
    }
    __syncthreads();
    if (t == 0) s[2047] = 0;
    for (int d = 1; d < 2048; d <<= 1) {
        offset >>= 1;
        __syncthreads();
        if (t < d) {
            int ai = offset * (2 * t + 1) - 1;
            int bi = offset * (2 * t + 2) - 1;
            int tmp = s[ai]; s[ai] = s[bi]; s[bi] += tmp;
        }
    }
    __syncthreads();
}

__global__ __launch_bounds__(1024) void topk_kernel(const float* __restrict__ score, int n, int kk,
                                                    int* __restrict__ newpos, int* __restrict__ oldidx) {
    __shared__ float sc[2048];
    __shared__ float sv[2048];
    __shared__ int   si[2048];
    __shared__ int   sh_cG;
    int g = blockIdx.x;
    int t = threadIdx.x;
    for (int i = t; i < 2048; i += 1024) {
        float v = (i < n) ? score[g * n + i] : -1e30f;
        sc[i] = v;
        sv[i] = v;
    }
    __syncthreads();
    for (int k2 = 2; k2 <= 2048; k2 <<= 1) {
        for (int j = k2 >> 1; j > 0; j >>= 1) {
            for (int i = t; i < 2048; i += 1024) {
                int ixj = i ^ j;
                if (ixj > i) {
                    bool up = ((i & k2) == 0);
                    float a = sv[i], b = sv[ixj];
                    if ((a > b) == up) { sv[i] = b; sv[ixj] = a; }
                }
            }
            __syncthreads();
        }
    }
    float thr = sv[2048 - kk];
    if (t == 0) sh_cG = 0;
    __syncthreads();
    int loc = 0;
    for (int i = t; i < 2048; i += 1024) if (sc[i] > thr) loc++;
    if (loc) atomicAdd(&sh_cG, loc);
    __syncthreads();
    int needEq = kk - sh_cG;
    for (int i = t; i < 2048; i += 1024) si[i] = (sc[i] == thr) ? 1 : 0;
    scan2048(si, t);
    int keep[2];
#pragma unroll
    for (int u = 0; u < 2; u++) {
        int i = t + u * 1024;
        float v = sc[i];
        keep[u] = (v > thr) || (v == thr && si[i] < needEq);
    }
    __syncthreads();
#pragma unroll
    for (int u = 0; u < 2; u++) si[t + u * 1024] = keep[u];
    scan2048(si, t);
#pragma unroll
    for (int u = 0; u < 2; u++) {
        int i = t + u * 1024;
        if (i < n) {
            if (keep[u]) {
                int pos = g * kk + si[i];
                newpos[g * n + i] = pos;
                oldidx[pos] = g * n + i;
            } else {
                newpos[g * n + i] = -1;
            }
        }
    }
}

// ---------------- fused pool copy + partial readout ----------------
#define RCHUNK 128
__global__ void pool_readout(const float* __restrict__ Hc, const float* __restrict__ score,
                             const int* __restrict__ oldidx, float* __restrict__ Xn,
                             float* __restrict__ pmax, float* __restrict__ psum,
                             int k, int S) {
    int g = blockIdx.x, chunk = blockIdx.y, f = threadIdx.x;
    int base = chunk * RCHUNK;
    int end = min(base + RCHUNK, k);
    float mx = -1e30f, sm = 0.f;
    for (int r = base; r < end; r++) {
        int pos = g * k + r;
        int o = oldidx[pos];
        float v = Hc[(size_t)o * H + f] * score[o];
        Xn[(size_t)pos * H + f] = v;
        mx = fmaxf(mx, v);
        sm += v;
    }
    pmax[(size_t)(g * S + chunk) * H + f] = mx;
    psum[(size_t)(g * S + chunk) * H + f] = sm;
}

__global__ void readout_combine(const float* __restrict__ pmax, const float* __restrict__ psum,
                                float* __restrict__ accz, int S, int k, int first) {
    int g = blockIdx.x, f = threadIdx.x;
    float mx = -1e30f, sm = 0.f;
    for (int c = 0; c < S; c++) {
        mx = fmaxf(mx, pmax[(size_t)(g * S + c) * H + f]);
        sm += psum[(size_t)(g * S + c) * H + f];
    }
    float mean = sm / (float)k;
    if (first) {
        accz[g * 256 + f] = mx;
        accz[g * 256 + 128 + f] = mean;
    } else {
        accz[g * 256 + f] += mx;
        accz[g * 256 + 128 + f] += mean;
    }
}

// ---------------- fused MLP head ----------------
__global__ void mlp_head(const float* __restrict__ accz,
                         const float* __restrict__ lw1, const float* __restrict__ lb1,
                         const float* __restrict__ lw2, const float* __restrict__ lb2,
                         const float* __restrict__ lw3, const float* __restrict__ lb3,
                         float* __restrict__ out) {
    int g = blockIdx.x, j = threadIdx.x;  // 128 threads
    __shared__ float z0[256], z1s[128], z2s[64];
    z0[j] = accz[g * 256 + j];
    z0[128 + j] = accz[g * 256 + 128 + j];
    __syncthreads();
    float a = lb1[j];
    for (int q = 0; q < 256; q++) a += z0[q] * lw1[q * 128 + j];
    z1s[j] = fmaxf(a, 0.f);
    __syncthreads();
    if (j < 64) {
        float a2 = lb2[j];
        for (int q = 0; q < 128; q++) a2 += z1s[q] * lw2[q * 64 + j];
        z2s[j] = fmaxf(a2, 0.f);
    }
    __syncthreads();
    if (j < 124) {
        float a3 = lb3[j];
        for (int q = 0; q < 64; q++) a3 += z2s[q] * lw3[q * ACT + j];
        out[g * ACT + j] = 1.f / (1.f + expf(-a3));
    }
}

// ---------------- host orchestration ----------------
extern "C" void kernel_launch(void* const* d_in, const int* in_sizes, int n_in,
                              void* d_out, int out_size) {
    const float* x   = (const float*)d_in[0];
    const int* src   = (const int*)d_in[1];
    const int* dst   = (const int*)d_in[2];
    const float* W1  = (const float*)d_in[3];
    const float* b1  = (const float*)d_in[4];
    const float* W2  = (const float*)d_in[5];
    const float* b2  = (const float*)d_in[6];
    const float* W3  = (const float*)d_in[7];
    const float* b3  = (const float*)d_in[8];
    const float* p1  = (const float*)d_in[9];
    const float* p2  = (const float*)d_in[10];
    const float* p3  = (const float*)d_in[11];
    const float* lw1 = (const float*)d_in[12];
    const float* lb1 = (const float*)d_in[13];
    const float* lw2 = (const float*)d_in[14];
    const float* lb2 = (const float*)d_in[15];
    const float* lw3 = (const float*)d_in[16];
    const float* lb3 = (const float*)d_in[17];
    float* out = (float*)d_out;

    float *buf0, *buf1, *score, *pnorm, *accz, *pmax, *psum;
    int *cnt, *rowstart, *esrc, *edst, *evalid, *eadj, *newpos, *oldidx, *bsums;
    cudaGetSymbolAddress((void**)&buf0, g_buf0);
    cudaGetSymbolAddress((void**)&buf1, g_buf1);
    cudaGetSymbolAddress((void**)&score, g_score);
    cudaGetSymbolAddress((void**)&pnorm, g_pnorm);
    cudaGetSymbolAddress((void**)&accz, g_accz);
    cudaGetSymbolAddress((void**)&pmax, g_pmax);
    cudaGetSymbolAddress((void**)&psum, g_psum);
    cudaGetSymbolAddress((void**)&cnt, g_cnt);
    cudaGetSymbolAddress((void**)&rowstart, g_rowstart);
    cudaGetSymbolAddress((void**)&esrc, g_esrc);
    cudaGetSymbolAddress((void**)&edst, g_edst);
    cudaGetSymbolAddress((void**)&evalid, g_evalid);
    cudaGetSymbolAddress((void**)&eadj, g_eadj);
    cudaGetSymbolAddress((void**)&newpos, g_newpos);
    cudaGetSymbolAddress((void**)&oldidx, g_oldidx);
    cudaGetSymbolAddress((void**)&bsums, g_bsums);

    const int npg_[3] = {2048, 1639, 1312};
    const int kk_[3]  = {K1, K2, K3};
    const int nn[4]   = {131072, 64 * K1, 64 * K2, 64 * K3};
    const int SS[3]   = {(K1 + RCHUNK - 1) / RCHUNK, (K2 + RCHUNK - 1) / RCHUNK,
                         (K3 + RCHUNK - 1) / RCHUNK};
    const float* Ws[3] = {W1, W2, W3};
    const float* bs[3] = {b1, b2, b3};
    const float* ps[3] = {p1, p2, p3};

    pnorm_kernel<<<1, 128>>>(p1, p2, p3, pnorm);
    cudaMemsetAsync(cnt, 0, nn[0] * sizeof(int));
    edge_init_count<<<EDG / 256, 256>>>(src, dst, esrc, edst, evalid, cnt);

    const float* prev_pool = nullptr;
    for (int l = 0; l < 3; l++) {
        int n = nn[l], k = kk_[l], npg = npg_[l], S = SS[l];
        float* mm = (l & 1) ? buf1 : buf0;   // gemm output / pooled output
        float* gt = (l & 1) ? buf0 : buf1;   // gather output

        if (l > 0)
            sgemm_tf32<<<(n + 127) / 128, 256>>>(prev_pool, Ws[l], mm, n);

        // CSR build (cnt already counted)
        int nb = (n + 511) / 512;
        scan_block<<<nb, 512>>>(cnt, rowstart, bsums, n);
        scan_sums<<<1, 512>>>(bsums, nb);
        scan_add<<<(n + 255) / 256, 256>>>(rowstart, bsums, n);
        edge_fill<<<EDG / 256, 256>>>(esrc, edst, evalid, rowstart, eadj);

        if (l == 0)
            gcn_l0<<<n, 128>>>(x, W1, b1, eadj, rowstart, cnt, p1, pnorm, gt, score);
        else
            gcn_gather<<<n, 128>>>(mm, eadj, rowstart, cnt, bs[l], ps[l], pnorm, l, gt, score);

        topk_kernel<<<BGR, 1024>>>(score, npg, k, newpos, oldidx);

        dim3 prg(BGR, S);
        pool_readout<<<prg, 128>>>(gt, score, oldidx, mm, pmax, psum, k, S);
        readout_combine<<<BGR, 128>>>(pmax, psum, accz, S, k, (l == 0) ? 1 : 0);

        if (l < 2) {
            cudaMemsetAsync(cnt, 0, nn[l + 1] * sizeof(int));
            remap_count<<<EDG / 256, 256>>>(esrc, edst, evalid, newpos, cnt);
        }
        prev_pool = mm;
    }

    mlp_head<<<BGR, 128>>>(accz, lw1, lb1, lw2, lb2, lw3, lb3, out);
}

// round 3
// speedup vs baseline: 2.2798x; 1.4109x over previous
#include <cuda_runtime.h>
#include <math.h>
#include <stdint.h>

#define BGR 64
#define EDG  524288
#define H 128
#define K1 1639
#define K2 1312
#define K3 1050
#define ACT 124
#define NMAX 131072

// ---------------- scratch ----------------
__device__ float g_buf0[(size_t)NMAX * H];   // GEMM outputs
__device__ float g_buf1[(size_t)NMAX * H];   // gather outputs
__device__ int   g_cnt[NMAX];
__device__ int   g_rowstart[NMAX];
__device__ int   g_esrc[EDG];
__device__ int   g_edst[EDG];
__device__ int   g_evalid[EDG];
__device__ int   g_eadj[EDG];
__device__ float g_score[NMAX];
__device__ int   g_newpos[NMAX];
__device__ int   g_oldidx[NMAX];
__device__ int   g_bsums[256];
__device__ float g_pnorm[4];
__device__ float g_accz[BGR * 256];
__device__ float g_pmax[BGR * 13 * H];
__device__ float g_psum[BGR * 13 * H];

// ---------------- tiny utility kernels ----------------
__global__ void pnorm_kernel(const float* p1, const float* p2, const float* p3, float* out) {
    __shared__ float red[128];
    const float* ps[3] = {p1, p2, p3};
    int t = threadIdx.x;
    for (int l = 0; l < 3; l++) {
        red[t] = ps[l][t] * ps[l][t];
        __syncthreads();
        for (int off = 64; off; off >>= 1) {
            if (t < off) red[t] += red[t + off];
            __syncthreads();
        }
        if (t == 0) out[l] = sqrtf(red[0]);
        __syncthreads();
    }
}

__global__ void edge_init_count(const int* __restrict__ src, const int* __restrict__ dst,
                                int* __restrict__ esrc, int* __restrict__ edst,
                                int* __restrict__ evalid, int* __restrict__ cnt) {
    int e = blockIdx.x * blockDim.x + threadIdx.x;
    int s = src[e], d = dst[e];
    esrc[e] = s;
    edst[e] = d;
    evalid[e] = 1;
    atomicAdd(&cnt[d], 1);
}

__global__ void remap_count(int* __restrict__ esrc, int* __restrict__ edst,
                            int* __restrict__ evalid, const int* __restrict__ newpos,
                            int* __restrict__ cnt) {
    int e = blockIdx.x * blockDim.x + threadIdx.x;
    if (evalid[e]) {
        int s = newpos[esrc[e]];
        int d = newpos[edst[e]];
        if (s >= 0 && d >= 0) {
            esrc[e] = s; edst[e] = d;
            atomicAdd(&cnt[d], 1);
        } else {
            esrc[e] = 0; edst[e] = 0; evalid[e] = 0;
        }
    }
}

// ---------------- CSR scan: block-local scans + 256-wide offset scan ----------------
__global__ void scan_block(const int* __restrict__ cnt, int* __restrict__ rowstart,
                           int* __restrict__ bsums, int n) {
    __shared__ int s[512];
    int t = threadIdx.x;
    int i = blockIdx.x * 512 + t;
    s[t] = (i < n) ? cnt[i] : 0;
    int offset = 1;
    for (int d = 256; d > 0; d >>= 1) {
        __syncthreads();
        if (t < d) {
            int ai = offset * (2 * t + 1) - 1;
            int bi = offset * (2 * t + 2) - 1;
            s[bi] += s[ai];
        }
        offset <<= 1;
    }
    __syncthreads();
    if (t == 0) { bsums[blockIdx.x] = s[511]; s[511] = 0; }
    for (int d = 1; d < 512; d <<= 1) {
        offset >>= 1;
        __syncthreads();
        if (t < d) {
            int ai = offset * (2 * t + 1) - 1;
            int bi = offset * (2 * t + 2) - 1;
            int tmp = s[ai]; s[ai] = s[bi]; s[bi] += tmp;
        }
    }
    __syncthreads();
    if (i < n) rowstart[i] = s[t];
}

__global__ void scan_sums_small(int* __restrict__ bsums, int nb) {
    __shared__ int s[256];
    int t = threadIdx.x;
    int v = (t < nb) ? bsums[t] : 0;
    s[t] = v;
    __syncthreads();
    for (int off = 1; off < 256; off <<= 1) {
        int add = (t >= off) ? s[t - off] : 0;
        __syncthreads();
        s[t] += add;
        __syncthreads();
    }
    if (t < nb) bsums[t] = s[t] - v;   // exclusive
}

__global__ void edge_fill(const int* __restrict__ esrc, const int* __restrict__ edst,
                          const int* __restrict__ evalid, int* __restrict__ rowstart,
                          const int* __restrict__ boff, int* __restrict__ eadj) {
    int e = blockIdx.x * blockDim.x + threadIdx.x;
    if (evalid[e]) {
        int d = edst[e];
        int pos = atomicAdd(&rowstart[d], 1) + boff[d >> 9];
        eadj[pos] = esrc[e];
    }
}

// ---------------- tf32 tensor-core GEMM with fused pooling gather ----------------
// Y[pos,128] = (Hc[oldidx[pos]] * score[oldidx[pos]]) @ W[128,128]
__device__ __forceinline__ uint32_t f2tf(float f) {
    uint32_t u;
    asm("cvt.rna.tf32.f32 %0, %1;" : "=r"(u) : "f"(f));
    return u;
}

__device__ __forceinline__ void mma_tf32(float* c, uint32_t a0, uint32_t a1, uint32_t a2,
                                         uint32_t a3, uint32_t b0, uint32_t b1) {
    asm volatile(
        "mma.sync.aligned.m16n8k8.row.col.f32.tf32.tf32.f32 "
        "{%0,%1,%2,%3},{%4,%5,%6,%7},{%8,%9},{%0,%1,%2,%3};"
        : "+f"(c[0]), "+f"(c[1]), "+f"(c[2]), "+f"(c[3])
        : "r"(a0), "r"(a1), "r"(a2), "r"(a3), "r"(b0), "r"(b1));
}

__global__ __launch_bounds__(256) void sgemm_pool_tf32(const float* __restrict__ Hc,
                                                       const int* __restrict__ oldidx,
                                                       const float* __restrict__ score,
                                                       const float* __restrict__ W,
                                                       float* __restrict__ Y, int n) {
    __shared__ __align__(16) uint32_t As[2][128][12];
    __shared__ __align__(16) uint32_t Bs[2][8][136];
    int bm = blockIdx.x * 128;
    int tid = threadIdx.x;
    int lane = tid & 31, warp = tid >> 5;
    int wr = warp >> 1, wc = warp & 1;

    float acc[2][8][4];
#pragma unroll
    for (int m = 0; m < 2; m++)
#pragma unroll
        for (int nt = 0; nt < 8; nt++)
#pragma unroll
            for (int q = 0; q < 4; q++) acc[m][nt][q] = 0.f;

    int arow = tid >> 1;
    int ac = (tid & 1) * 4;
    int browk = tid >> 5;
    int bcol = (tid & 31) * 4;

    // per-thread pooled-row source (fixed across k-steps)
    int pos = bm + arow;
    bool rv = (pos < n);
    int o = 0;
    float sc = 0.f;
    if (rv) { o = oldidx[pos]; sc = score[o]; }
    const float* arowp = Hc + (size_t)o * 128;

    {
        float4 va = make_float4(0.f, 0.f, 0.f, 0.f);
        if (rv) va = *(const float4*)&arowp[ac];
        float4 vb = *(const float4*)&W[(size_t)browk * 128 + bcol];
        uint4 ua = make_uint4(f2tf(va.x * sc), f2tf(va.y * sc), f2tf(va.z * sc), f2tf(va.w * sc));
        uint4 ub = make_uint4(f2tf(vb.x), f2tf(vb.y), f2tf(vb.z), f2tf(vb.w));
        *(uint4*)&As[0][arow][ac] = ua;
        *(uint4*)&Bs[0][browk][bcol] = ub;
    }
    __syncthreads();

    int r0 = wr * 32 + (lane >> 2);
    int cA = lane & 3;

    for (int ks = 0; ks < 16; ks++) {
        int cur = ks & 1;
        float4 va, vb;
        if (ks < 15) {
            int k0 = (ks + 1) * 8;
            va = make_float4(0.f, 0.f, 0.f, 0.f);
            if (rv) va = *(const float4*)&arowp[k0 + ac];
            vb = *(const float4*)&W[(size_t)(k0 + browk) * 128 + bcol];
        }
        uint32_t bfr[8][2];
#pragma unroll
        for (int nt = 0; nt < 8; nt++) {
            int col = wc * 64 + nt * 8 + (lane >> 2);
            bfr[nt][0] = Bs[cur][lane & 3][col];
            bfr[nt][1] = Bs[cur][(lane & 3) + 4][col];
        }
#pragma unroll
        for (int m = 0; m < 2; m++) {
            uint32_t a0 = As[cur][r0 + m * 16][cA];
            uint32_t a1 = As[cur][r0 + m * 16 + 8][cA];
            uint32_t a2 = As[cur][r0 + m * 16][cA + 4];
            uint32_t a3 = As[cur][r0 + m * 16 + 8][cA + 4];
#pragma unroll
            for (int nt = 0; nt < 8; nt++)
                mma_tf32(acc[m][nt], a0, a1, a2, a3, bfr[nt][0], bfr[nt][1]);
        }
        if (ks < 15) {
            int nxt = cur ^ 1;
            uint4 ua = make_uint4(f2tf(va.x * sc), f2tf(va.y * sc), f2tf(va.z * sc), f2tf(va.w * sc));
            uint4 ub = make_uint4(f2tf(vb.x), f2tf(vb.y), f2tf(vb.z), f2tf(vb.w));
            *(uint4*)&As[nxt][arow][ac] = ua;
            *(uint4*)&Bs[nxt][browk][bcol] = ub;
            __syncthreads();
        }
    }

#pragma unroll
    for (int m = 0; m < 2; m++) {
#pragma unroll
        for (int nt = 0; nt < 8; nt++) {
            int row = bm + wr * 32 + m * 16 + (lane >> 2);
            int col = wc * 64 + nt * 8 + (lane & 3) * 2;
            if (row < n)
                *(float2*)&Y[(size_t)row * 128 + col] = make_float2(acc[m][nt][0], acc[m][nt][1]);
            if (row + 8 < n)
                *(float2*)&Y[(size_t)(row + 8) * 128 + col] = make_float2(acc[m][nt][2], acc[m][nt][3]);
        }
    }
}

// ---------------- warp-per-node GCN gather + relu + score ----------------
__device__ __forceinline__ float warp_sum(float v) {
#pragma unroll
    for (int off = 16; off; off >>= 1) v += __shfl_xor_sync(0xffffffffu, v, off);
    return v;
}

__global__ __launch_bounds__(256) void gcn_l0_warp(const float* __restrict__ x,
                                                   const float* __restrict__ W1,
                                                   const float* __restrict__ b1,
                                                   const int* __restrict__ eadj,
                                                   const int* __restrict__ rowend,
                                                   const int* __restrict__ boff,
                                                   const int* __restrict__ cnt,
                                                   const float* __restrict__ p,
                                                   const float* __restrict__ pnorm,
                                                   float* __restrict__ Out,
                                                   float* __restrict__ score, int n) {
    int i = blockIdx.x * 8 + (threadIdx.x >> 5);
    if (i >= n) return;
    int lane = threadIdx.x & 31;
    int fb = lane * 4;
    float4 w0 = *(const float4*)&W1[fb];
    float4 w1 = *(const float4*)&W1[128 + fb];
    float4 w2 = *(const float4*)&W1[256 + fb];
    float4 w3 = *(const float4*)&W1[384 + fb];
    float4 bb = *(const float4*)&b1[fb];
    float4 pp = *(const float4*)&p[fb];

    int c = cnt[i];
    float di = rsqrtf((float)(c + 1));
    float4 xi = *(const float4*)&x[(size_t)i * 4];
    float s0 = di * di;
    float4 acc;
    acc.x = (xi.x * w0.x + xi.y * w1.x + xi.z * w2.x + xi.w * w3.x) * s0 + bb.x;
    acc.y = (xi.x * w0.y + xi.y * w1.y + xi.z * w2.y + xi.w * w3.y) * s0 + bb.y;
    acc.z = (xi.x * w0.z + xi.y * w1.z + xi.z * w2.z + xi.w * w3.z) * s0 + bb.z;
    acc.w = (xi.x * w0.w + xi.y * w1.w + xi.z * w2.w + xi.w * w3.w) * s0 + bb.w;

    int st = rowend[i] + boff[i >> 9] - c;
    int e = 0;
    for (; e + 1 < c; e += 2) {
        int sA = eadj[st + e], sB = eadj[st + e + 1];
        float4 xa = *(const float4*)&x[(size_t)sA * 4];
        float4 xb = *(const float4*)&x[(size_t)sB * 4];
        float dA = rsqrtf((float)(cnt[sA] + 1)) * di;
        float dB = rsqrtf((float)(cnt[sB] + 1)) * di;
        acc.x += (xa.x * w0.x + xa.y * w1.x + xa.z * w2.x + xa.w * w3.x) * dA
               + (xb.x * w0.x + xb.y * w1.x + xb.z * w2.x + xb.w * w3.x) * dB;
        acc.y += (xa.x * w0.y + xa.y * w1.y + xa.z * w2.y + xa.w * w3.y) * dA
               + (xb.x * w0.y + xb.y * w1.y + xb.z * w2.y + xb.w * w3.y) * dB;
        acc.z += (xa.x * w0.z + xa.y * w1.z + xa.z * w2.z + xa.w * w3.z) * dA
               + (xb.x * w0.z + xb.y * w1.z + xb.z * w2.z + xb.w * w3.z) * dB;
        acc.w += (xa.x * w0.w + xa.y * w1.w + xa.z * w2.w + xa.w * w3.w) * dA
               + (xb.x * w0.w + xb.y * w1.w + xb.z * w2.w + xb.w * w3.w) * dB;
    }
    if (e < c) {
        int sA = eadj[st + e];
        float4 xa = *(const float4*)&x[(size_t)sA * 4];
        float dA = rsqrtf((float)(cnt[sA] + 1)) * di;
        acc.x += (xa.x * w0.x + xa.y * w1.x + xa.z * w2.x + xa.w * w3.x) * dA;
        acc.y += (xa.x * w0.y + xa.y * w1.y + xa.z * w2.y + xa.w * w3.y) * dA;
        acc.z += (xa.x * w0.z + xa.y * w1.z + xa.z * w2.z + xa.w * w3.z) * dA;
        acc.w += (xa.x * w0.w + xa.y * w1.w + xa.z * w2.w + xa.w * w3.w) * dA;
    }
    acc.x = fmaxf(acc.x, 0.f); acc.y = fmaxf(acc.y, 0.f);
    acc.z = fmaxf(acc.z, 0.f); acc.w = fmaxf(acc.w, 0.f);
    *(float4*)&Out[(size_t)i * H + fb] = acc;
    float sred = acc.x * pp.x + acc.y * pp.y + acc.z * pp.z + acc.w * pp.w;
    sred = warp_sum(sred);
    if (lane == 0) score[i] = tanhf(sred / pnorm[0]);
}

__global__ __launch_bounds__(256) void gcn_warp(const float* __restrict__ H2,
                                                const int* __restrict__ eadj,
                                                const int* __restrict__ rowend,
                                                const int* __restrict__ boff,
                                                const int* __restrict__ cnt,
                                                const float* __restrict__ bias,
                                                const float* __restrict__ p,
                                                const float* __restrict__ pnorm, int lvl,
                                                float* __restrict__ Out,
                                                float* __restrict__ score, int n) {
    int i = blockIdx.x * 8 + (threadIdx.x >> 5);
    if (i >= n) return;
    int lane = threadIdx.x & 31;
    int fb = lane * 4;
    int c = cnt[i];
    float di = rsqrtf((float)(c + 1));
    float4 h = *(const float4*)&H2[(size_t)i * H + fb];
    float4 bb = *(const float4*)&bias[fb];
    float s0 = di * di;
    float4 acc = make_float4(h.x * s0 + bb.x, h.y * s0 + bb.y, h.z * s0 + bb.z, h.w * s0 + bb.w);

    int st = rowend[i] + boff[i >> 9] - c;
    int e = 0;
    for (; e + 1 < c; e += 2) {
        int sA = eadj[st + e], sB = eadj[st + e + 1];
        float4 va = *(const float4*)&H2[(size_t)sA * H + fb];
        float4 vb = *(const float4*)&H2[(size_t)sB * H + fb];
        float dA = rsqrtf((float)(cnt[sA] + 1)) * di;
        float dB = rsqrtf((float)(cnt[sB] + 1)) * di;
        acc.x += va.x * dA + vb.x * dB;
        acc.y += va.y * dA + vb.y * dB;
        acc.z += va.z * dA + vb.z * dB;
        acc.w += va.w * dA + vb.w * dB;
    }
    if (e < c) {
        int sA = eadj[st + e];
        float4 va = *(const float4*)&H2[(size_t)sA * H + fb];
        float dA = rsqrtf((float)(cnt[sA] + 1)) * di;
        acc.x += va.x * dA; acc.y += va.y * dA; acc.z += va.z * dA; acc.w += va.w * dA;
    }
    acc.x = fmaxf(acc.x, 0.f); acc.y = fmaxf(acc.y, 0.f);
    acc.z = fmaxf(acc.z, 0.f); acc.w = fmaxf(acc.w, 0.f);
    *(float4*)&Out[(size_t)i * H + fb] = acc;
    float4 pp = *(const float4*)&p[fb];
    float sred = acc.x * pp.x + acc.y * pp.y + acc.z * pp.z + acc.w * pp.w;
    sred = warp_sum(sred);
    if (lane == 0) score[i] = tanhf(sred / pnorm[lvl]);
}

// ---------------- top-k per graph ----------------
__device__ __forceinline__ void scan2048(int* s, int t) {
    int offset = 1;
    for (int d = 1024; d > 0; d >>= 1) {
        __syncthreads();
        if (t < d) {
            int ai = offset * (2 * t + 1) - 1;
            int bi = offset * (2 * t + 2) - 1;
            s[bi] += s[ai];
        }
        offset <<= 1;
    }
    __syncthreads();
    if (t == 0) s[2047] = 0;
    for (int d = 1; d < 2048; d <<= 1) {
        offset >>= 1;
        __syncthreads();
        if (t < d) {
            int ai = offset * (2 * t + 1) - 1;
            int bi = offset * (2 * t + 2) - 1;
            int tmp = s[ai]; s[ai] = s[bi]; s[bi] += tmp;
        }
    }
    __syncthreads();
}

__global__ __launch_bounds__(1024) void topk_kernel(const float* __restrict__ score, int n, int kk,
                                                    int* __restrict__ newpos, int* __restrict__ oldidx) {
    __shared__ float sc[2048];
    __shared__ float sv[2048];
    __shared__ int   si[2048];
    __shared__ int   sh_cG;
    int g = blockIdx.x;
    int t = threadIdx.x;
    for (int i = t; i < 2048; i += 1024) {
        float v = (i < n) ? score[g * n + i] : -1e30f;
        sc[i] = v;
        sv[i] = v;
    }
    __syncthreads();
    for (int k2 = 2; k2 <= 2048; k2 <<= 1) {
        for (int j = k2 >> 1; j > 0; j >>= 1) {
            for (int i = t; i < 2048; i += 1024) {
                int ixj = i ^ j;
                if (ixj > i) {
                    bool up = ((i & k2) == 0);
                    float a = sv[i], b = sv[ixj];
                    if ((a > b) == up) { sv[i] = b; sv[ixj] = a; }
                }
            }
            __syncthreads();
        }
    }
    float thr = sv[2048 - kk];
    if (t == 0) sh_cG = 0;
    __syncthreads();
    int loc = 0;
    for (int i = t; i < 2048; i += 1024) if (sc[i] > thr) loc++;
    if (loc) atomicAdd(&sh_cG, loc);
    __syncthreads();
    int needEq = kk - sh_cG;
    for (int i = t; i < 2048; i += 1024) si[i] = (sc[i] == thr) ? 1 : 0;
    scan2048(si, t);
    int keep[2];
#pragma unroll
    for (int u = 0; u < 2; u++) {
        int i = t + u * 1024;
        float v = sc[i];
        keep[u] = (v > thr) || (v == thr && si[i] < needEq);
    }
    __syncthreads();
#pragma unroll
    for (int u = 0; u < 2; u++) si[t + u * 1024] = keep[u];
    scan2048(si, t);
#pragma unroll
    for (int u = 0; u < 2; u++) {
        int i = t + u * 1024;
        if (i < n) {
            if (keep[u]) {
                int pos = g * kk + si[i];
                newpos[g * n + i] = pos;
                oldidx[pos] = g * n + i;
            } else {
                newpos[g * n + i] = -1;
            }
        }
    }
}

// ---------------- readout over pooled rows (no materialization) ----------------
#define RCHUNK 128
__global__ void readout_partial(const float* __restrict__ Hc, const float* __restrict__ score,
                                const int* __restrict__ oldidx,
                                float* __restrict__ pmax, float* __restrict__ psum,
                                int k, int S) {
    int g = blockIdx.x, chunk = blockIdx.y, f = threadIdx.x;
    int base = chunk * RCHUNK;
    int end = min(base + RCHUNK, k);
    float mx = -1e30f, sm = 0.f;
    for (int r = base; r < end; r++) {
        int o = oldidx[g * k + r];
        float v = Hc[(size_t)o * H + f] * score[o];
        mx = fmaxf(mx, v);
        sm += v;
    }
    pmax[(size_t)(g * S + chunk) * H + f] = mx;
    psum[(size_t)(g * S + chunk) * H + f] = sm;
}

__global__ void readout_combine(const float* __restrict__ pmax, const float* __restrict__ psum,
                                float* __restrict__ accz, int S, int k, int first) {
    int g = blockIdx.x, f = threadIdx.x;
    float mx = -1e30f, sm = 0.f;
    for (int c = 0; c < S; c++) {
        mx = fmaxf(mx, pmax[(size_t)(g * S + c) * H + f]);
        sm += psum[(size_t)(g * S + c) * H + f];
    }
    float mean = sm / (float)k;
    if (first) {
        accz[g * 256 + f] = mx;
        accz[g * 256 + 128 + f] = mean;
    } else {
        accz[g * 256 + f] += mx;
        accz[g * 256 + 128 + f] += mean;
    }
}

// ---------------- fused MLP head ----------------
__global__ void mlp_head(const float* __restrict__ accz,
                         const float* __restrict__ lw1, const float* __restrict__ lb1,
                         const float* __restrict__ lw2, const float* __restrict__ lb2,
                         const float* __restrict__ lw3, const float* __restrict__ lb3,
                         float* __restrict__ out) {
    int g = blockIdx.x, j = threadIdx.x;
    __shared__ float z0[256], z1s[128], z2s[64];
    z0[j] = accz[g * 256 + j];
    z0[128 + j] = accz[g * 256 + 128 + j];
    __syncthreads();
    float a = lb1[j];
    for (int q = 0; q < 256; q++) a += z0[q] * lw1[q * 128 + j];
    z1s[j] = fmaxf(a, 0.f);
    __syncthreads();
    if (j < 64) {
        float a2 = lb2[j];
        for (int q = 0; q < 128; q++) a2 += z1s[q] * lw2[q * 64 + j];
        z2s[j] = fmaxf(a2, 0.f);
    }
    __syncthreads();
    if (j < 124) {
        float a3 = lb3[j];
        for (int q = 0; q < 64; q++) a3 += z2s[q] * lw3[q * ACT + j];
        out[g * ACT + j] = 1.f / (1.f + expf(-a3));
    }
}

// ---------------- host orchestration ----------------
extern "C" void kernel_launch(void* const* d_in, const int* in_sizes, int n_in,
                              void* d_out, int out_size) {
    const float* x   = (const float*)d_in[0];
    const int* src   = (const int*)d_in[1];
    const int* dst   = (const int*)d_in[2];
    const float* W1  = (const float*)d_in[3];
    const float* b1  = (const float*)d_in[4];
    const float* W2  = (const float*)d_in[5];
    const float* b2  = (const float*)d_in[6];
    const float* W3  = (const float*)d_in[7];
    const float* b3  = (const float*)d_in[8];
    const float* p1  = (const float*)d_in[9];
    const float* p2  = (const float*)d_in[10];
    const float* p3  = (const float*)d_in[11];
    const float* lw1 = (const float*)d_in[12];
    const float* lb1 = (const float*)d_in[13];
    const float* lw2 = (const float*)d_in[14];
    const float* lb2 = (const float*)d_in[15];
    const float* lw3 = (const float*)d_in[16];
    const float* lb3 = (const float*)d_in[17];
    float* out = (float*)d_out;

    float *buf0, *buf1, *score, *pnorm, *accz, *pmax, *psum;
    int *cnt, *rowstart, *esrc, *edst, *evalid, *eadj, *newpos, *oldidx, *bsums;
    cudaGetSymbolAddress((void**)&buf0, g_buf0);
    cudaGetSymbolAddress((void**)&buf1, g_buf1);
    cudaGetSymbolAddress((void**)&score, g_score);
    cudaGetSymbolAddress((void**)&pnorm, g_pnorm);
    cudaGetSymbolAddress((void**)&accz, g_accz);
    cudaGetSymbolAddress((void**)&pmax, g_pmax);
    cudaGetSymbolAddress((void**)&psum, g_psum);
    cudaGetSymbolAddress((void**)&cnt, g_cnt);
    cudaGetSymbolAddress((void**)&rowstart, g_rowstart);
    cudaGetSymbolAddress((void**)&esrc, g_esrc);
    cudaGetSymbolAddress((void**)&edst, g_edst);
    cudaGetSymbolAddress((void**)&evalid, g_evalid);
    cudaGetSymbolAddress((void**)&eadj, g_eadj);
    cudaGetSymbolAddress((void**)&newpos, g_newpos);
    cudaGetSymbolAddress((void**)&oldidx, g_oldidx);
    cudaGetSymbolAddress((void**)&bsums, g_bsums);

    const int npg_[3] = {2048, 1639, 1312};
    const int kk_[3]  = {K1, K2, K3};
    const int nn[4]   = {131072, 64 * K1, 64 * K2, 64 * K3};
    const int SS[3]   = {(K1 + RCHUNK - 1) / RCHUNK, (K2 + RCHUNK - 1) / RCHUNK,
                         (K3 + RCHUNK - 1) / RCHUNK};
    const float* Ws[3] = {W1, W2, W3};
    const float* bs[3] = {b1, b2, b3};
    const float* ps[3] = {p1, p2, p3};

    pnorm_kernel<<<1, 128>>>(p1, p2, p3, pnorm);
    cudaMemsetAsync(cnt, 0, nn[0] * sizeof(int));
    edge_init_count<<<EDG / 256, 256>>>(src, dst, esrc, edst, evalid, cnt);

    for (int l = 0; l < 3; l++) {
        int n = nn[l], k = kk_[l], npg = npg_[l], S = SS[l];

        if (l > 0)
            sgemm_pool_tf32<<<(n + 127) / 128, 256>>>(buf1, oldidx, score, Ws[l], buf0, n);

        int nb = (n + 511) / 512;
        scan_block<<<nb, 512>>>(cnt, rowstart, bsums, n);
        scan_sums_small<<<1, 256>>>(bsums, nb);
        edge_fill<<<EDG / 256, 256>>>(esrc, edst, evalid, rowstart, bsums, eadj);

        if (l == 0)
            gcn_l0_warp<<<(n + 7) / 8, 256>>>(x, W1, b1, eadj, rowstart, bsums, cnt,
                                              p1, pnorm, buf1, score, n);
        else
            gcn_warp<<<(n + 7) / 8, 256>>>(buf0, eadj, rowstart, bsums, cnt,
                                           bs[l], ps[l], pnorm, l, buf1, score, n);

        topk_kernel<<<BGR, 1024>>>(score, npg, k, newpos, oldidx);

        dim3 prg(BGR, S);
        readout_partial<<<prg, 128>>>(buf1, score, oldidx, pmax, psum, k, S);
        readout_combine<<<BGR, 128>>>(pmax, psum, accz, S, k, (l == 0) ? 1 : 0);

        if (l < 2) {
            cudaMemsetAsync(cnt, 0, nn[l + 1] * sizeof(int));
            remap_count<<<EDG / 256, 256>>>(esrc, edst, evalid, newpos, cnt);
        }
    }

    mlp_head<<<BGR, 128>>>(accz, lw1, lb1, lw2, lb2, lw3, lb3, out);
}

// round 4
// speedup vs baseline: 2.4427x; 1.0714x over previous
#include <cuda_runtime.h>
#include <math.h>
#include <stdint.h>

#define BGR 64
#define EDG  524288
#define H 128
#define K1 1639
#define K2 1312
#define K3 1050
#define ACT 124
#define NMAX 131072

// ---------------- scratch ----------------
__device__ float g_buf0[(size_t)NMAX * H];   // GEMM outputs (pre-scaled by dis)
__device__ float g_buf1[(size_t)NMAX * H];   // gather outputs (h, post-relu)
__device__ float g_xs[(size_t)NMAX * 4];     // x * dis (level 0)
__device__ int   g_cnt[NMAX];
__device__ int   g_rowstart[NMAX];
__device__ int   g_esrc[EDG];
__device__ int   g_edst[EDG];
__device__ int   g_evalid[EDG];
__device__ int   g_eadj[EDG];
__device__ float g_score[NMAX];
__device__ int   g_newpos[NMAX];
__device__ int   g_oldidx[NMAX];
__device__ int   g_bsums[256];
__device__ float g_pnorm[4];
__device__ float g_accz[BGR * 256];
__device__ float g_pmax[BGR * 13 * H];
__device__ float g_psum[BGR * 13 * H];

// ---------------- tiny utility kernels ----------------
__global__ void pnorm_kernel(const float* p1, const float* p2, const float* p3, float* out) {
    __shared__ float red[128];
    const float* ps[3] = {p1, p2, p3};
    int t = threadIdx.x;
    for (int l = 0; l < 3; l++) {
        red[t] = ps[l][t] * ps[l][t];
        __syncthreads();
        for (int off = 64; off; off >>= 1) {
            if (t < off) red[t] += red[t + off];
            __syncthreads();
        }
        if (t == 0) out[l] = sqrtf(red[0]);
        __syncthreads();
    }
}

__global__ void edge_init_count(const int* __restrict__ src, const int* __restrict__ dst,
                                int* __restrict__ esrc, int* __restrict__ edst,
                                int* __restrict__ evalid, int* __restrict__ cnt) {
    int e = blockIdx.x * blockDim.x + threadIdx.x;
    int s = src[e], d = dst[e];
    esrc[e] = s;
    edst[e] = d;
    evalid[e] = 1;
    atomicAdd(&cnt[d], 1);
}

__global__ void remap_count(int* __restrict__ esrc, int* __restrict__ edst,
                            int* __restrict__ evalid, const int* __restrict__ newpos,
                            int* __restrict__ cnt) {
    int e = blockIdx.x * blockDim.x + threadIdx.x;
    if (evalid[e]) {
        int s = newpos[esrc[e]];
        int d = newpos[edst[e]];
        if (s >= 0 && d >= 0) {
            esrc[e] = s; edst[e] = d;
            atomicAdd(&cnt[d], 1);
        } else {
            esrc[e] = 0; edst[e] = 0; evalid[e] = 0;
        }
    }
}

// ---------------- CSR scan; at l0 also emits xs = x * dis ----------------
__global__ void scan_block(const int* __restrict__ cnt, int* __restrict__ rowstart,
                           int* __restrict__ bsums, int n,
                           const float* __restrict__ x, float* __restrict__ xs) {
    __shared__ int s[512];
    int t = threadIdx.x;
    int i = blockIdx.x * 512 + t;
    int v = (i < n) ? cnt[i] : 0;
    s[t] = v;
    if (x && i < n) {
        float di = rsqrtf((float)(v + 1));
        float4 xi = *(const float4*)&x[(size_t)i * 4];
        xi.x *= di; xi.y *= di; xi.z *= di; xi.w *= di;
        *(float4*)&xs[(size_t)i * 4] = xi;
    }
    int offset = 1;
    for (int d = 256; d > 0; d >>= 1) {
        __syncthreads();
        if (t < d) {
            int ai = offset * (2 * t + 1) - 1;
            int bi = offset * (2 * t + 2) - 1;
            s[bi] += s[ai];
        }
        offset <<= 1;
    }
    __syncthreads();
    if (t == 0) { bsums[blockIdx.x] = s[511]; s[511] = 0; }
    for (int d = 1; d < 512; d <<= 1) {
        offset >>= 1;
        __syncthreads();
        if (t < d) {
            int ai = offset * (2 * t + 1) - 1;
            int bi = offset * (2 * t + 2) - 1;
            int tmp = s[ai]; s[ai] = s[bi]; s[bi] += tmp;
        }
    }
    __syncthreads();
    if (i < n) rowstart[i] = s[t];
}

__global__ void scan_sums_small(int* __restrict__ bsums, int nb) {
    __shared__ int s[256];
    int t = threadIdx.x;
    int v = (t < nb) ? bsums[t] : 0;
    s[t] = v;
    __syncthreads();
    for (int off = 1; off < 256; off <<= 1) {
        int add = (t >= off) ? s[t - off] : 0;
        __syncthreads();
        s[t] += add;
        __syncthreads();
    }
    if (t < nb) bsums[t] = s[t] - v;   // exclusive
}

__global__ void edge_fill(const int* __restrict__ esrc, const int* __restrict__ edst,
                          const int* __restrict__ evalid, int* __restrict__ rowstart,
                          const int* __restrict__ boff, int* __restrict__ eadj) {
    int e = blockIdx.x * blockDim.x + threadIdx.x;
    if (evalid[e]) {
        int d = edst[e];
        int pos = atomicAdd(&rowstart[d], 1) + boff[d >> 9];
        eadj[pos] = esrc[e];
    }
}

// ---------------- tf32 GEMM + pooling gather + dis epilogue ----------------
// Y[pos,:] = ((Hc[oldidx[pos]] * score[oldidx[pos]]) @ W) * dis[pos]
__device__ __forceinline__ uint32_t f2tf(float f) {
    uint32_t u;
    asm("cvt.rna.tf32.f32 %0, %1;" : "=r"(u) : "f"(f));
    return u;
}

__device__ __forceinline__ void mma_tf32(float* c, uint32_t a0, uint32_t a1, uint32_t a2,
                                         uint32_t a3, uint32_t b0, uint32_t b1) {
    asm volatile(
        "mma.sync.aligned.m16n8k8.row.col.f32.tf32.tf32.f32 "
        "{%0,%1,%2,%3},{%4,%5,%6,%7},{%8,%9},{%0,%1,%2,%3};"
        : "+f"(c[0]), "+f"(c[1]), "+f"(c[2]), "+f"(c[3])
        : "r"(a0), "r"(a1), "r"(a2), "r"(a3), "r"(b0), "r"(b1));
}

__global__ __launch_bounds__(256) void sgemm_pool_tf32(const float* __restrict__ Hc,
                                                       const int* __restrict__ oldidx,
                                                       const float* __restrict__ score,
                                                       const int* __restrict__ cnt,
                                                       const float* __restrict__ W,
                                                       float* __restrict__ Y, int n) {
    __shared__ __align__(16) uint32_t As[2][128][12];
    __shared__ __align__(16) uint32_t Bs[2][8][136];
    int bm = blockIdx.x * 128;
    int tid = threadIdx.x;
    int lane = tid & 31, warp = tid >> 5;
    int wr = warp >> 1, wc = warp & 1;

    float acc[2][8][4];
#pragma unroll
    for (int m = 0; m < 2; m++)
#pragma unroll
        for (int nt = 0; nt < 8; nt++)
#pragma unroll
            for (int q = 0; q < 4; q++) acc[m][nt][q] = 0.f;

    int arow = tid >> 1;
    int ac = (tid & 1) * 4;
    int browk = tid >> 5;
    int bcol = (tid & 31) * 4;

    int pos = bm + arow;
    bool rv = (pos < n);
    int o = 0;
    float sc = 0.f;
    if (rv) { o = oldidx[pos]; sc = score[o]; }
    const float* arowp = Hc + (size_t)o * 128;

    {
        float4 va = make_float4(0.f, 0.f, 0.f, 0.f);
        if (rv) va = *(const float4*)&arowp[ac];
        float4 vb = *(const float4*)&W[(size_t)browk * 128 + bcol];
        uint4 ua = make_uint4(f2tf(va.x * sc), f2tf(va.y * sc), f2tf(va.z * sc), f2tf(va.w * sc));
        uint4 ub = make_uint4(f2tf(vb.x), f2tf(vb.y), f2tf(vb.z), f2tf(vb.w));
        *(uint4*)&As[0][arow][ac] = ua;
        *(uint4*)&Bs[0][browk][bcol] = ub;
    }
    __syncthreads();

    int r0 = wr * 32 + (lane >> 2);
    int cA = lane & 3;

    for (int ks = 0; ks < 16; ks++) {
        int cur = ks & 1;
        float4 va, vb;
        if (ks < 15) {
            int k0 = (ks + 1) * 8;
            va = make_float4(0.f, 0.f, 0.f, 0.f);
            if (rv) va = *(const float4*)&arowp[k0 + ac];
            vb = *(const float4*)&W[(size_t)(k0 + browk) * 128 + bcol];
        }
        uint32_t bfr[8][2];
#pragma unroll
        for (int nt = 0; nt < 8; nt++) {
            int col = wc * 64 + nt * 8 + (lane >> 2);
            bfr[nt][0] = Bs[cur][lane & 3][col];
            bfr[nt][1] = Bs[cur][(lane & 3) + 4][col];
        }
#pragma unroll
        for (int m = 0; m < 2; m++) {
            uint32_t a0 = As[cur][r0 + m * 16][cA];
            uint32_t a1 = As[cur][r0 + m * 16 + 8][cA];
            uint32_t a2 = As[cur][r0 + m * 16][cA + 4];
            uint32_t a3 = As[cur][r0 + m * 16 + 8][cA + 4];
#pragma unroll
            for (int nt = 0; nt < 8; nt++)
                mma_tf32(acc[m][nt], a0, a1, a2, a3, bfr[nt][0], bfr[nt][1]);
        }
        if (ks < 15) {
            int nxt = cur ^ 1;
            uint4 ua = make_uint4(f2tf(va.x * sc), f2tf(va.y * sc), f2tf(va.z * sc), f2tf(va.w * sc));
            uint4 ub = make_uint4(f2tf(vb.x), f2tf(vb.y), f2tf(vb.z), f2tf(vb.w));
            *(uint4*)&As[nxt][arow][ac] = ua;
            *(uint4*)&Bs[nxt][browk][bcol] = ub;
            __syncthreads();
        }
    }

#pragma unroll
    for (int m = 0; m < 2; m++) {
        int row = bm + wr * 32 + m * 16 + (lane >> 2);
        float d0 = 0.f, d1 = 0.f;
        if (row < n)     d0 = rsqrtf((float)(cnt[row] + 1));
        if (row + 8 < n) d1 = rsqrtf((float)(cnt[row + 8] + 1));
#pragma unroll
        for (int nt = 0; nt < 8; nt++) {
            int col = wc * 64 + nt * 8 + (lane & 3) * 2;
            if (row < n)
                *(float2*)&Y[(size_t)row * 128 + col] =
                    make_float2(acc[m][nt][0] * d0, acc[m][nt][1] * d0);
            if (row + 8 < n)
                *(float2*)&Y[(size_t)(row + 8) * 128 + col] =
                    make_float2(acc[m][nt][2] * d1, acc[m][nt][3] * d1);
        }
    }
}

// ---------------- warp-per-node GCN gather + relu + score ----------------
__device__ __forceinline__ float warp_sum(float v) {
#pragma unroll
    for (int off = 16; off; off >>= 1) v += __shfl_xor_sync(0xffffffffu, v, off);
    return v;
}

// level 0: rows of xs are pre-scaled; sum 4-vectors then one matvec
__global__ __launch_bounds__(256) void gcn_l0_warp(const float* __restrict__ xs,
                                                   const float* __restrict__ W1,
                                                   const float* __restrict__ b1,
                                                   const int* __restrict__ eadj,
                                                   const int* __restrict__ rowend,
                                                   const int* __restrict__ boff,
                                                   const int* __restrict__ cnt,
                                                   const float* __restrict__ p,
                                                   const float* __restrict__ pnorm,
                                                   float* __restrict__ Out,
                                                   float* __restrict__ score, int n) {
    int i = blockIdx.x * 8 + (threadIdx.x >> 5);
    if (i >= n) return;
    int lane = threadIdx.x & 31;
    int fb = lane * 4;

    int c = cnt[i];
    float di = rsqrtf((float)(c + 1));
    float4 sum = *(const float4*)&xs[(size_t)i * 4];
    int st = rowend[i] + boff[i >> 9] - c;
    int e = 0;
    for (; e + 1 < c; e += 2) {
        int sA = eadj[st + e], sB = eadj[st + e + 1];
        float4 xa = *(const float4*)&xs[(size_t)sA * 4];
        float4 xb = *(const float4*)&xs[(size_t)sB * 4];
        sum.x += xa.x + xb.x; sum.y += xa.y + xb.y;
        sum.z += xa.z + xb.z; sum.w += xa.w + xb.w;
    }
    if (e < c) {
        int sA = eadj[st + e];
        float4 xa = *(const float4*)&xs[(size_t)sA * 4];
        sum.x += xa.x; sum.y += xa.y; sum.z += xa.z; sum.w += xa.w;
    }

    float4 w0 = *(const float4*)&W1[fb];
    float4 w1 = *(const float4*)&W1[128 + fb];
    float4 w2 = *(const float4*)&W1[256 + fb];
    float4 w3 = *(const float4*)&W1[384 + fb];
    float4 bb = *(const float4*)&b1[fb];
    float4 acc;
    acc.x = fmaxf((sum.x * w0.x + sum.y * w1.x + sum.z * w2.x + sum.w * w3.x) * di + bb.x, 0.f);
    acc.y = fmaxf((sum.x * w0.y + sum.y * w1.y + sum.z * w2.y + sum.w * w3.y) * di + bb.y, 0.f);
    acc.z = fmaxf((sum.x * w0.z + sum.y * w1.z + sum.z * w2.z + sum.w * w3.z) * di + bb.z, 0.f);
    acc.w = fmaxf((sum.x * w0.w + sum.y * w1.w + sum.z * w2.w + sum.w * w3.w) * di + bb.w, 0.f);
    *(float4*)&Out[(size_t)i * H + fb] = acc;

    float4 pp = *(const float4*)&p[fb];
    float sred = acc.x * pp.x + acc.y * pp.y + acc.z * pp.z + acc.w * pp.w;
    sred = warp_sum(sred);
    if (lane == 0) score[i] = tanhf(sred / pnorm[0]);
}

// levels 1,2: Ys rows pre-scaled by their dis; out = relu((Ys_i + sum Ys_s)*di + b)
__global__ __launch_bounds__(256) void gcn_warp(const float* __restrict__ Ys,
                                                const int* __restrict__ eadj,
                                                const int* __restrict__ rowend,
                                                const int* __restrict__ boff,
                                                const int* __restrict__ cnt,
                                                const float* __restrict__ bias,
                                                const float* __restrict__ p,
                                                const float* __restrict__ pnorm, int lvl,
                                                float* __restrict__ Out,
                                                float* __restrict__ score, int n) {
    int i = blockIdx.x * 8 + (threadIdx.x >> 5);
    if (i >= n) return;
    int lane = threadIdx.x & 31;
    int fb = lane * 4;
    int c = cnt[i];
    float di = rsqrtf((float)(c + 1));
    float4 acc = *(const float4*)&Ys[(size_t)i * H + fb];

    int st = rowend[i] + boff[i >> 9] - c;
    int e = 0;
    for (; e + 1 < c; e += 2) {
        int sA = eadj[st + e], sB = eadj[st + e + 1];
        float4 va = *(const float4*)&Ys[(size_t)sA * H + fb];
        float4 vb = *(const float4*)&Ys[(size_t)sB * H + fb];
        acc.x += va.x + vb.x; acc.y += va.y + vb.y;
        acc.z += va.z + vb.z; acc.w += va.w + vb.w;
    }
    if (e < c) {
        int sA = eadj[st + e];
        float4 va = *(const float4*)&Ys[(size_t)sA * H + fb];
        acc.x += va.x; acc.y += va.y; acc.z += va.z; acc.w += va.w;
    }
    float4 bb = *(const float4*)&bias[fb];
    acc.x = fmaxf(acc.x * di + bb.x, 0.f);
    acc.y = fmaxf(acc.y * di + bb.y, 0.f);
    acc.z = fmaxf(acc.z * di + bb.z, 0.f);
    acc.w = fmaxf(acc.w * di + bb.w, 0.f);
    *(float4*)&Out[(size_t)i * H + fb] = acc;

    float4 pp = *(const float4*)&p[fb];
    float sred = acc.x * pp.x + acc.y * pp.y + acc.z * pp.z + acc.w * pp.w;
    sred = warp_sum(sred);
    if (lane == 0) score[i] = tanhf(sred / pnorm[lvl]);
}

// ---------------- top-k per graph ----------------
__device__ __forceinline__ void scan2048(int* s, int t) {
    int offset = 1;
    for (int d = 1024; d > 0; d >>= 1) {
        __syncthreads();
        if (t < d) {
            int ai = offset * (2 * t + 1) - 1;
            int bi = offset * (2 * t + 2) - 1;
            s[bi] += s[ai];
        }
        offset <<= 1;
    }
    __syncthreads();
    if (t == 0) s[2047] = 0;
    for (int d = 1; d < 2048; d <<= 1) {
        offset >>= 1;
        __syncthreads();
        if (t < d) {
            int ai = offset * (2 * t + 1) - 1;
            int bi = offset * (2 * t + 2) - 1;
            int tmp = s[ai]; s[ai] = s[bi]; s[bi] += tmp;
        }
    }
    __syncthreads();
}

__global__ __launch_bounds__(1024) void topk_kernel(const float* __restrict__ score, int n, int kk,
                                                    int* __restrict__ newpos, int* __restrict__ oldidx) {
    __shared__ float sc[2048];
    __shared__ float sv[2048];
    __shared__ int   si[2048];
    __shared__ int   sh_cG;
    int g = blockIdx.x;
    int t = threadIdx.x;
    for (int i = t; i < 2048; i += 1024) {
        float v = (i < n) ? score[g * n + i] : -1e30f;
        sc[i] = v;
        sv[i] = v;
    }
    __syncthreads();
    for (int k2 = 2; k2 <= 2048; k2 <<= 1) {
        for (int j = k2 >> 1; j > 0; j >>= 1) {
            for (int i = t; i < 2048; i += 1024) {
                int ixj = i ^ j;
                if (ixj > i) {
                    bool up = ((i & k2) == 0);
                    float a = sv[i], b = sv[ixj];
                    if ((a > b) == up) { sv[i] = b; sv[ixj] = a; }
                }
            }
            __syncthreads();
        }
    }
    float thr = sv[2048 - kk];
    if (t == 0) sh_cG = 0;
    __syncthreads();
    int loc = 0;
    for (int i = t; i < 2048; i += 1024) if (sc[i] > thr) loc++;
    if (loc) atomicAdd(&sh_cG, loc);
    __syncthreads();
    int needEq = kk - sh_cG;
    for (int i = t; i < 2048; i += 1024) si[i] = (sc[i] == thr) ? 1 : 0;
    scan2048(si, t);
    int keep[2];
#pragma unroll
    for (int u = 0; u < 2; u++) {
        int i = t + u * 1024;
        float v = sc[i];
        keep[u] = (v > thr) || (v == thr && si[i] < needEq);
    }
    __syncthreads();
#pragma unroll
    for (int u = 0; u < 2; u++) si[t + u * 1024] = keep[u];
    scan2048(si, t);
#pragma unroll
    for (int u = 0; u < 2; u++) {
        int i = t + u * 1024;
        if (i < n) {
            if (keep[u]) {
                int pos = g * kk + si[i];
                newpos[g * n + i] = pos;
                oldidx[pos] = g * n + i;
            } else {
                newpos[g * n + i] = -1;
            }
        }
    }
}

// ---------------- readout ----------------
#define RCHUNK 128
__global__ void readout_partial(const float* __restrict__ Hc, const float* __restrict__ score,
                                const int* __restrict__ oldidx,
                                float* __restrict__ pmax, float* __restrict__ psum,
                                int k, int S) {
    int g = blockIdx.x, chunk = blockIdx.y, f = threadIdx.x;
    int base = chunk * RCHUNK;
    int end = min(base + RCHUNK, k);
    float mx = -1e30f, sm = 0.f;
    for (int r = base; r < end; r++) {
        int o = oldidx[g * k + r];
        float v = Hc[(size_t)o * H + f] * score[o];
        mx = fmaxf(mx, v);
        sm += v;
    }
    pmax[(size_t)(g * S + chunk) * H + f] = mx;
    psum[(size_t)(g * S + chunk) * H + f] = sm;
}

__global__ void readout_combine(const float* __restrict__ pmax, const float* __restrict__ psum,
                                float* __restrict__ accz, int S, int k, int first) {
    int g = blockIdx.x, f = threadIdx.x;
    float mx = -1e30f, sm = 0.f;
    for (int c = 0; c < S; c++) {
        mx = fmaxf(mx, pmax[(size_t)(g * S + c) * H + f]);
        sm += psum[(size_t)(g * S + c) * H + f];
    }
    float mean = sm / (float)k;
    if (first) {
        accz[g * 256 + f] = mx;
        accz[g * 256 + 128 + f] = mean;
    } else {
        accz[g * 256 + f] += mx;
        accz[g * 256 + 128 + f] += mean;
    }
}

// ---------------- fused MLP head ----------------
__global__ void mlp_head(const float* __restrict__ accz,
                         const float* __restrict__ lw1, const float* __restrict__ lb1,
                         const float* __restrict__ lw2, const float* __restrict__ lb2,
                         const float* __restrict__ lw3, const float* __restrict__ lb3,
                         float* __restrict__ out) {
    int g = blockIdx.x, j = threadIdx.x;
    __shared__ float z0[256], z1s[128], z2s[64];
    z0[j] = accz[g * 256 + j];
    z0[128 + j] = accz[g * 256 + 128 + j];
    __syncthreads();
    float a = lb1[j];
    for (int q = 0; q < 256; q++) a += z0[q] * lw1[q * 128 + j];
    z1s[j] = fmaxf(a, 0.f);
    __syncthreads();
    if (j < 64) {
        float a2 = lb2[j];
        for (int q = 0; q < 128; q++) a2 += z1s[q] * lw2[q * 64 + j];
        z2s[j] = fmaxf(a2, 0.f);
    }
    __syncthreads();
    if (j < 124) {
        float a3 = lb3[j];
        for (int q = 0; q < 64; q++) a3 += z2s[q] * lw3[q * ACT + j];
        out[g * ACT + j] = 1.f / (1.f + expf(-a3));
    }
}

// ---------------- host orchestration ----------------
extern "C" void kernel_launch(void* const* d_in, const int* in_sizes, int n_in,
                              void* d_out, int out_size) {
    const float* x   = (const float*)d_in[0];
    const int* src   = (const int*)d_in[1];
    const int* dst   = (const int*)d_in[2];
    const float* W1  = (const float*)d_in[3];
    const float* b1  = (const float*)d_in[4];
    const float* W2  = (const float*)d_in[5];
    const float* b2  = (const float*)d_in[6];
    const float* W3  = (const float*)d_in[7];
    const float* b3  = (const float*)d_in[8];
    const float* p1  = (const float*)d_in[9];
    const float* p2  = (const float*)d_in[10];
    const float* p3  = (const float*)d_in[11];
    const float* lw1 = (const float*)d_in[12];
    const float* lb1 = (const float*)d_in[13];
    const float* lw2 = (const float*)d_in[14];
    const float* lb2 = (const float*)d_in[15];
    const float* lw3 = (const float*)d_in[16];
    const float* lb3 = (const float*)d_in[17];
    float* out = (float*)d_out;

    float *buf0, *buf1, *xs, *score, *pnorm, *accz, *pmax, *psum;
    int *cnt, *rowstart, *esrc, *edst, *evalid, *eadj, *newpos, *oldidx, *bsums;
    cudaGetSymbolAddress((void**)&buf0, g_buf0);
    cudaGetSymbolAddress((void**)&buf1, g_buf1);
    cudaGetSymbolAddress((void**)&xs, g_xs);
    cudaGetSymbolAddress((void**)&score, g_score);
    cudaGetSymbolAddress((void**)&pnorm, g_pnorm);
    cudaGetSymbolAddress((void**)&accz, g_accz);
    cudaGetSymbolAddress((void**)&pmax, g_pmax);
    cudaGetSymbolAddress((void**)&psum, g_psum);
    cudaGetSymbolAddress((void**)&cnt, g_cnt);
    cudaGetSymbolAddress((void**)&rowstart, g_rowstart);
    cudaGetSymbolAddress((void**)&esrc, g_esrc);
    cudaGetSymbolAddress((void**)&edst, g_edst);
    cudaGetSymbolAddress((void**)&evalid, g_evalid);
    cudaGetSymbolAddress((void**)&eadj, g_eadj);
    cudaGetSymbolAddress((void**)&newpos, g_newpos);
    cudaGetSymbolAddress((void**)&oldidx, g_oldidx);
    cudaGetSymbolAddress((void**)&bsums, g_bsums);

    const int npg_[3] = {2048, 1639, 1312};
    const int kk_[3]  = {K1, K2, K3};
    const int nn[4]   = {131072, 64 * K1, 64 * K2, 64 * K3};
    const int SS[3]   = {(K1 + RCHUNK - 1) / RCHUNK, (K2 + RCHUNK - 1) / RCHUNK,
                         (K3 + RCHUNK - 1) / RCHUNK};
    const float* Ws[3] = {W1, W2, W3};
    const float* bs[3] = {b1, b2, b3};
    const float* ps[3] = {p1, p2, p3};

    pnorm_kernel<<<1, 128>>>(p1, p2, p3, pnorm);
    cudaMemsetAsync(cnt, 0, nn[0] * sizeof(int));
    edge_init_count<<<EDG / 256, 256>>>(src, dst, esrc, edst, evalid, cnt);

    for (int l = 0; l < 3; l++) {
        int n = nn[l], k = kk_[l], npg = npg_[l], S = SS[l];

        if (l > 0)
            sgemm_pool_tf32<<<(n + 127) / 128, 256>>>(buf1, oldidx, score, cnt, Ws[l], buf0, n);

        int nb = (n + 511) / 512;
        scan_block<<<nb, 512>>>(cnt, rowstart, bsums, n,
                                (l == 0) ? x : nullptr, xs);
        scan_sums_small<<<1, 256>>>(bsums, nb);
        edge_fill<<<EDG / 256, 256>>>(esrc, edst, evalid, rowstart, bsums, eadj);

        if (l == 0)
            gcn_l0_warp<<<(n + 7) / 8, 256>>>(xs, W1, b1, eadj, rowstart, bsums, cnt,
                                              p1, pnorm, buf1, score, n);
        else
            gcn_warp<<<(n + 7) / 8, 256>>>(buf0, eadj, rowstart, bsums, cnt,
                                           bs[l], ps[l], pnorm, l, buf1, score, n);

        topk_kernel<<<BGR, 1024>>>(score, npg, k, newpos, oldidx);

        dim3 prg(BGR, S);
        readout_partial<<<prg, 128>>>(buf1, score, oldidx, pmax, psum, k, S);
        readout_combine<<<BGR, 128>>>(pmax, psum, accz, S, k, (l == 0) ? 1 : 0);

        if (l < 2) {
            cudaMemsetAsync(cnt, 0, nn[l + 1] * sizeof(int));
            remap_count<<<EDG / 256, 256>>>(esrc, edst, evalid, newpos, cnt);
        }
    }

    mlp_head<<<BGR, 128>>>(accz, lw1, lb1, lw2, lb2, lw3, lb3, out);
}

// round 6
// speedup vs baseline: 2.7643x; 1.1317x over previous
#include <cuda_runtime.h>
#include <math.h>
#include <stdint.h>

#define BGR 64
#define EDG  524288
#define H 128
#define K1 1639
#define K2 1312
#define K3 1050
#define ACT 124
#define NMAX 131072

// ---------------- scratch ----------------
__device__ float g_buf0[(size_t)NMAX * H];   // GEMM outputs (pre-scaled by dis)
__device__ float g_buf1[(size_t)NMAX * H];   // gather outputs (h, post-relu)
__device__ float g_xs[(size_t)NMAX * 4];     // x * dis (level 0)
__device__ int   g_cnt[NMAX];
__device__ int   g_rowstart[NMAX];
__device__ int   g_esrc[EDG];
__device__ int   g_edst[EDG];
__device__ int   g_evalid[EDG];
__device__ int   g_eadj[EDG];
__device__ float g_score[NMAX];
__device__ int   g_newpos[NMAX];
__device__ int   g_oldidx[NMAX];
__device__ int   g_bsums[256];
__device__ float g_pnorm[4];
__device__ float g_accz[BGR * 256];

// ---------------- tiny utility kernels ----------------
__global__ void pnorm_kernel(const float* p1, const float* p2, const float* p3, float* out) {
    __shared__ float red[128];
    const float* ps[3] = {p1, p2, p3};
    int t = threadIdx.x;
    for (int l = 0; l < 3; l++) {
        red[t] = ps[l][t] * ps[l][t];
        __syncthreads();
        for (int off = 64; off; off >>= 1) {
            if (t < off) red[t] += red[t + off];
            __syncthreads();
        }
        if (t == 0) out[l] = sqrtf(red[0]);
        __syncthreads();
    }
}

__global__ void edge_init_count(const int* __restrict__ src, const int* __restrict__ dst,
                                int* __restrict__ esrc, int* __restrict__ edst,
                                int* __restrict__ evalid, int* __restrict__ cnt) {
    int e = blockIdx.x * blockDim.x + threadIdx.x;
    int s = src[e], d = dst[e];
    esrc[e] = s;
    edst[e] = d;
    evalid[e] = 1;
    atomicAdd(&cnt[d], 1);
}

__global__ void remap_count(int* __restrict__ esrc, int* __restrict__ edst,
                            int* __restrict__ evalid, const int* __restrict__ newpos,
                            int* __restrict__ cnt) {
    int e = blockIdx.x * blockDim.x + threadIdx.x;
    if (evalid[e]) {
        int s = newpos[esrc[e]];
        int d = newpos[edst[e]];
        if (s >= 0 && d >= 0) {
            esrc[e] = s; edst[e] = d;
            atomicAdd(&cnt[d], 1);
        } else {
            esrc[e] = 0; edst[e] = 0; evalid[e] = 0;
        }
    }
}

// ---------------- CSR scan (3-kernel, proven) ----------------
__global__ void scan_block(const int* __restrict__ cnt, int* __restrict__ rowstart,
                           int* __restrict__ bsums, int n,
                           const float* __restrict__ x, float* __restrict__ xs) {
    __shared__ int s[512];
    int t = threadIdx.x;
    int i = blockIdx.x * 512 + t;
    int v = (i < n) ? cnt[i] : 0;
    s[t] = v;
    if (x && i < n) {
        float di = rsqrtf((float)(v + 1));
        float4 xi = *(const float4*)&x[(size_t)i * 4];
        xi.x *= di; xi.y *= di; xi.z *= di; xi.w *= di;
        *(float4*)&xs[(size_t)i * 4] = xi;
    }
    int offset = 1;
    for (int d = 256; d > 0; d >>= 1) {
        __syncthreads();
        if (t < d) {
            int ai = offset * (2 * t + 1) - 1;
            int bi = offset * (2 * t + 2) - 1;
            s[bi] += s[ai];
        }
        offset <<= 1;
    }
    __syncthreads();
    if (t == 0) { bsums[blockIdx.x] = s[511]; s[511] = 0; }
    for (int d = 1; d < 512; d <<= 1) {
        offset >>= 1;
        __syncthreads();
        if (t < d) {
            int ai = offset * (2 * t + 1) - 1;
            int bi = offset * (2 * t + 2) - 1;
            int tmp = s[ai]; s[ai] = s[bi]; s[bi] += tmp;
        }
    }
    __syncthreads();
    if (i < n) rowstart[i] = s[t];
}

__global__ void scan_sums_small(int* __restrict__ bsums, int nb) {
    __shared__ int s[256];
    int t = threadIdx.x;
    int v = (t < nb) ? bsums[t] : 0;
    s[t] = v;
    __syncthreads();
    for (int off = 1; off < 256; off <<= 1) {
        int add = (t >= off) ? s[t - off] : 0;
        __syncthreads();
        s[t] += add;
        __syncthreads();
    }
    if (t < nb) bsums[t] = s[t] - v;   // exclusive
}

__global__ void edge_fill(const int* __restrict__ esrc, const int* __restrict__ edst,
                          const int* __restrict__ evalid, int* __restrict__ rowstart,
                          const int* __restrict__ boff, int* __restrict__ eadj) {
    int e = blockIdx.x * blockDim.x + threadIdx.x;
    if (evalid[e]) {
        int d = edst[e];
        int pos = atomicAdd(&rowstart[d], 1) + boff[d >> 9];
        eadj[pos] = esrc[e];
    }
}

// ---------------- tf32 GEMM + pooling gather + dis epilogue ----------------
__device__ __forceinline__ uint32_t f2tf(float f) {
    uint32_t u;
    asm("cvt.rna.tf32.f32 %0, %1;" : "=r"(u) : "f"(f));
    return u;
}

__device__ __forceinline__ void mma_tf32(float* c, uint32_t a0, uint32_t a1, uint32_t a2,
                                         uint32_t a3, uint32_t b0, uint32_t b1) {
    asm volatile(
        "mma.sync.aligned.m16n8k8.row.col.f32.tf32.tf32.f32 "
        "{%0,%1,%2,%3},{%4,%5,%6,%7},{%8,%9},{%0,%1,%2,%3};"
        : "+f"(c[0]), "+f"(c[1]), "+f"(c[2]), "+f"(c[3])
        : "r"(a0), "r"(a1), "r"(a2), "r"(a3), "r"(b0), "r"(b1));
}

__global__ __launch_bounds__(256) void sgemm_pool_tf32(const float* __restrict__ Hc,
                                                       const int* __restrict__ oldidx,
                                                       const float* __restrict__ score,
                                                       const int* __restrict__ cnt,
                                                       const float* __restrict__ W,
                                                       float* __restrict__ Y, int n) {
    __shared__ __align__(16) uint32_t As[2][128][12];
    __shared__ __align__(16) uint32_t Bs[2][8][136];
    int bm = blockIdx.x * 128;
    int tid = threadIdx.x;
    int lane = tid & 31, warp = tid >> 5;
    int wr = warp >> 1, wc = warp & 1;

    float acc[2][8][4];
#pragma unroll
    for (int m = 0; m < 2; m++)
#pragma unroll
        for (int nt = 0; nt < 8; nt++)
#pragma unroll
            for (int q = 0; q < 4; q++) acc[m][nt][q] = 0.f;

    int arow = tid >> 1;
    int ac = (tid & 1) * 4;
    int browk = tid >> 5;
    int bcol = (tid & 31) * 4;

    int pos = bm + arow;
    bool rv = (pos < n);
    int o = 0;
    float sc = 0.f;
    if (rv) { o = oldidx[pos]; sc = score[o]; }
    const float* arowp = Hc + (size_t)o * 128;

    {
        float4 va = make_float4(0.f, 0.f, 0.f, 0.f);
        if (rv) va = *(const float4*)&arowp[ac];
        float4 vb = *(const float4*)&W[(size_t)browk * 128 + bcol];
        uint4 ua = make_uint4(f2tf(va.x * sc), f2tf(va.y * sc), f2tf(va.z * sc), f2tf(va.w * sc));
        uint4 ub = make_uint4(f2tf(vb.x), f2tf(vb.y), f2tf(vb.z), f2tf(vb.w));
        *(uint4*)&As[0][arow][ac] = ua;
        *(uint4*)&Bs[0][browk][bcol] = ub;
    }
    __syncthreads();

    int r0 = wr * 32 + (lane >> 2);
    int cA = lane & 3;

    for (int ks = 0; ks < 16; ks++) {
        int cur = ks & 1;
        float4 va, vb;
        if (ks < 15) {
            int k0 = (ks + 1) * 8;
            va = make_float4(0.f, 0.f, 0.f, 0.f);
            if (rv) va = *(const float4*)&arowp[k0 + ac];
            vb = *(const float4*)&W[(size_t)(k0 + browk) * 128 + bcol];
        }
        uint32_t bfr[8][2];
#pragma unroll
        for (int nt = 0; nt < 8; nt++) {
            int col = wc * 64 + nt * 8 + (lane >> 2);
            bfr[nt][0] = Bs[cur][lane & 3][col];
            bfr[nt][1] = Bs[cur][(lane & 3) + 4][col];
        }
#pragma unroll
        for (int m = 0; m < 2; m++) {
            uint32_t a0 = As[cur][r0 + m * 16][cA];
            uint32_t a1 = As[cur][r0 + m * 16 + 8][cA];
            uint32_t a2 = As[cur][r0 + m * 16][cA + 4];
            uint32_t a3 = As[cur][r0 + m * 16 + 8][cA + 4];
#pragma unroll
            for (int nt = 0; nt < 8; nt++)
                mma_tf32(acc[m][nt], a0, a1, a2, a3, bfr[nt][0], bfr[nt][1]);
        }
        if (ks < 15) {
            int nxt = cur ^ 1;
            uint4 ua = make_uint4(f2tf(va.x * sc), f2tf(va.y * sc), f2tf(va.z * sc), f2tf(va.w * sc));
            uint4 ub = make_uint4(f2tf(vb.x), f2tf(vb.y), f2tf(vb.z), f2tf(vb.w));
            *(uint4*)&As[nxt][arow][ac] = ua;
            *(uint4*)&Bs[nxt][browk][bcol] = ub;
            __syncthreads();
        }
    }

#pragma unroll
    for (int m = 0; m < 2; m++) {
        int row = bm + wr * 32 + m * 16 + (lane >> 2);
        float d0 = 0.f, d1 = 0.f;
        if (row < n)     d0 = rsqrtf((float)(cnt[row] + 1));
        if (row + 8 < n) d1 = rsqrtf((float)(cnt[row + 8] + 1));
#pragma unroll
        for (int nt = 0; nt < 8; nt++) {
            int col = wc * 64 + nt * 8 + (lane & 3) * 2;
            if (row < n)
                *(float2*)&Y[(size_t)row * 128 + col] =
                    make_float2(acc[m][nt][0] * d0, acc[m][nt][1] * d0);
            if (row + 8 < n)
                *(float2*)&Y[(size_t)(row + 8) * 128 + col] =
                    make_float2(acc[m][nt][2] * d1, acc[m][nt][3] * d1);
        }
    }
}

// ---------------- warp-per-node GCN gather + relu + score ----------------
__device__ __forceinline__ float warp_sum(float v) {
#pragma unroll
    for (int off = 16; off; off >>= 1) v += __shfl_xor_sync(0xffffffffu, v, off);
    return v;
}

__global__ __launch_bounds__(256) void gcn_l0_warp(const float* __restrict__ xs,
                                                   const float* __restrict__ W1,
                                                   const float* __restrict__ b1,
                                                   const int* __restrict__ eadj,
                                                   const int* __restrict__ rowend,
                                                   const int* __restrict__ boff,
                                                   const int* __restrict__ cnt,
                                                   const float* __restrict__ p,
                                                   const float* __restrict__ pnorm,
                                                   float* __restrict__ Out,
                                                   float* __restrict__ score, int n) {
    int i = blockIdx.x * 8 + (threadIdx.x >> 5);
    if (i >= n) return;
    int lane = threadIdx.x & 31;
    int fb = lane * 4;

    int c = cnt[i];
    float di = rsqrtf((float)(c + 1));
    float4 sum = *(const float4*)&xs[(size_t)i * 4];
    int st = rowend[i] + boff[i >> 9] - c;
    int e = 0;
    for (; e + 1 < c; e += 2) {
        int sA = eadj[st + e], sB = eadj[st + e + 1];
        float4 xa = *(const float4*)&xs[(size_t)sA * 4];
        float4 xb = *(const float4*)&xs[(size_t)sB * 4];
        sum.x += xa.x + xb.x; sum.y += xa.y + xb.y;
        sum.z += xa.z + xb.z; sum.w += xa.w + xb.w;
    }
    if (e < c) {
        int sA = eadj[st + e];
        float4 xa = *(const float4*)&xs[(size_t)sA * 4];
        sum.x += xa.x; sum.y += xa.y; sum.z += xa.z; sum.w += xa.w;
    }

    float4 w0 = *(const float4*)&W1[fb];
    float4 w1 = *(const float4*)&W1[128 + fb];
    float4 w2 = *(const float4*)&W1[256 + fb];
    float4 w3 = *(const float4*)&W1[384 + fb];
    float4 bb = *(const float4*)&b1[fb];
    float4 acc;
    acc.x = fmaxf((sum.x * w0.x + sum.y * w1.x + sum.z * w2.x + sum.w * w3.x) * di + bb.x, 0.f);
    acc.y = fmaxf((sum.x * w0.y + sum.y * w1.y + sum.z * w2.y + sum.w * w3.y) * di + bb.y, 0.f);
    acc.z = fmaxf((sum.x * w0.z + sum.y * w1.z + sum.z * w2.z + sum.w * w3.z) * di + bb.z, 0.f);
    acc.w = fmaxf((sum.x * w0.w + sum.y * w1.w + sum.z * w2.w + sum.w * w3.w) * di + bb.w, 0.f);
    *(float4*)&Out[(size_t)i * H + fb] = acc;

    float4 pp = *(const float4*)&p[fb];
    float sred = acc.x * pp.x + acc.y * pp.y + acc.z * pp.z + acc.w * pp.w;
    sred = warp_sum(sred);
    if (lane == 0) score[i] = tanhf(sred / pnorm[0]);
}

__global__ __launch_bounds__(256) void gcn_warp(const float* __restrict__ Ys,
                                                const int* __restrict__ eadj,
                                                const int* __restrict__ rowend,
                                                const int* __restrict__ boff,
                                                const int* __restrict__ cnt,
                                                const float* __restrict__ bias,
                                                const float* __restrict__ p,
                                                const float* __restrict__ pnorm, int lvl,
                                                float* __restrict__ Out,
                                                float* __restrict__ score, int n) {
    int i = blockIdx.x * 8 + (threadIdx.x >> 5);
    if (i >= n) return;
    int lane = threadIdx.x & 31;
    int fb = lane * 4;
    int c = cnt[i];
    float di = rsqrtf((float)(c + 1));
    float4 acc = *(const float4*)&Ys[(size_t)i * H + fb];

    int st = rowend[i] + boff[i >> 9] - c;
    int e = 0;
    for (; e + 1 < c; e += 2) {
        int sA = eadj[st + e], sB = eadj[st + e + 1];
        float4 va = *(const float4*)&Ys[(size_t)sA * H + fb];
        float4 vb = *(const float4*)&Ys[(size_t)sB * H + fb];
        acc.x += va.x + vb.x; acc.y += va.y + vb.y;
        acc.z += va.z + vb.z; acc.w += va.w + vb.w;
    }
    if (e < c) {
        int sA = eadj[st + e];
        float4 va = *(const float4*)&Ys[(size_t)sA * H + fb];
        acc.x += va.x; acc.y += va.y; acc.z += va.z; acc.w += va.w;
    }
    float4 bb = *(const float4*)&bias[fb];
    acc.x = fmaxf(acc.x * di + bb.x, 0.f);
    acc.y = fmaxf(acc.y * di + bb.y, 0.f);
    acc.z = fmaxf(acc.z * di + bb.z, 0.f);
    acc.w = fmaxf(acc.w * di + bb.w, 0.f);
    *(float4*)&Out[(size_t)i * H + fb] = acc;

    float4 pp = *(const float4*)&p[fb];
    float sred = acc.x * pp.x + acc.y * pp.y + acc.z * pp.z + acc.w * pp.w;
    sred = warp_sum(sred);
    if (lane == 0) score[i] = tanhf(sred / pnorm[lvl]);
}

// ---------------- radix-select top-k ----------------
__device__ __forceinline__ uint32_t fmap(float f) {
    uint32_t u = __float_as_uint(f);
    return (u & 0x80000000u) ? ~u : (u | 0x80000000u);
}

// exclusive index-ordered prefix over 2048 flags (2 per thread); wsum: shared int[64]
__device__ __forceinline__ void bscan2048(bool f0, bool f1, int* wsum, int t,
                                          int& p0, int& p1) {
    int w = t >> 5, lane = t & 31;
    unsigned b0 = __ballot_sync(0xffffffffu, f0);
    unsigned b1 = __ballot_sync(0xffffffffu, f1);
    if (lane == 0) { wsum[w] = __popc(b0); wsum[32 + w] = __popc(b1); }
    __syncthreads();
    if (t < 32) {
        int a = wsum[t], b = wsum[32 + t];
        int ai = a;
#pragma unroll
        for (int o = 1; o < 32; o <<= 1) { int y = __shfl_up_sync(0xffffffffu, ai, o); if (t >= o) ai += y; }
        int atot = __shfl_sync(0xffffffffu, ai, 31);
        int bi = b;
#pragma unroll
        for (int o = 1; o < 32; o <<= 1) { int y = __shfl_up_sync(0xffffffffu, bi, o); if (t >= o) bi += y; }
        bi += atot;
        wsum[t] = ai - a;
        wsum[32 + t] = bi - b;
    }
    __syncthreads();
    unsigned lm = (1u << lane) - 1;
    p0 = wsum[w] + __popc(b0 & lm);
    p1 = wsum[32 + w] + __popc(b1 & lm);
    __syncthreads();
}

__global__ __launch_bounds__(1024) void topk_radix(const float* __restrict__ score, int n, int kk,
                                                   int* __restrict__ newpos,
                                                   int* __restrict__ oldidx) {
    __shared__ uint32_t keys[2048];
    __shared__ int hist[256];
    __shared__ int cumsh[256];
    __shared__ int wsum[64];
    __shared__ int sh_b, sh_g;
    int g = blockIdx.x, t = threadIdx.x;
    int i1 = t + 1024;
    keys[t]  = (t  < n) ? fmap(score[g * n + t])  : 0u;
    keys[i1] = (i1 < n) ? fmap(score[g * n + i1]) : 0u;
    __syncthreads();

    uint32_t prefix = 0;
    int remaining = kk;
    for (int shift = 24; shift >= 0; shift -= 8) {
        if (t < 256) hist[t] = 0;
        __syncthreads();
        uint32_t k0 = keys[t], k1v = keys[i1];
        bool m0 = (shift == 24) || ((k0  >> (shift + 8)) == (prefix >> (shift + 8)));
        bool m1 = (shift == 24) || ((k1v >> (shift + 8)) == (prefix >> (shift + 8)));
        if (m0) atomicAdd(&hist[(k0  >> shift) & 255], 1);
        if (m1) atomicAdd(&hist[(k1v >> shift) & 255], 1);
        __syncthreads();
        // descending cumulative: cumsh[t] = sum of hist[255-t .. 255]
        int v = (t < 256) ? hist[255 - t] : 0;
        int x = v;
#pragma unroll
        for (int o = 1; o < 32; o <<= 1) { int y = __shfl_up_sync(0xffffffffu, x, o); if ((t & 31) >= o) x += y; }
        if ((t & 31) == 31 && t < 256) wsum[t >> 5] = x;
        __syncthreads();
        if (t < 32) {
            int w = (t < 8) ? wsum[t] : 0;
#pragma unroll
            for (int o = 1; o < 8; o <<= 1) { int y = __shfl_up_sync(0xffffffffu, w, o); if (t >= o) w += y; }
            if (t < 8) wsum[t] = w;
        }
        __syncthreads();
        if (t < 256) cumsh[t] = x + ((t >= 32) ? wsum[(t >> 5) - 1] : 0);
        __syncthreads();
        if (t < 256) {
            int Cb = cumsh[t];
            int Cn = (t == 0) ? 0 : cumsh[t - 1];
            if (Cb >= remaining && Cn < remaining) { sh_b = 255 - t; sh_g = Cn; }
        }
        __syncthreads();
        prefix |= ((uint32_t)sh_b) << shift;
        remaining -= sh_g;
        __syncthreads();
    }
    uint32_t T = prefix;
    int needEq = remaining;

    bool e0 = (keys[t] == T), e1 = (keys[i1] == T);
    int q0, q1;
    bscan2048(e0, e1, wsum, t, q0, q1);
    bool keep0 = (keys[t]  > T) || (e0 && q0 < needEq);
    bool keep1 = (keys[i1] > T) || (e1 && q1 < needEq);
    int p0, p1;
    bscan2048(keep0, keep1, wsum, t, p0, p1);
    if (t < n) {
        if (keep0) { newpos[g * n + t] = g * kk + p0; oldidx[g * kk + p0] = g * n + t; }
        else newpos[g * n + t] = -1;
    }
    if (i1 < n) {
        if (keep1) { newpos[g * n + i1] = g * kk + p1; oldidx[g * kk + p1] = g * n + i1; }
        else newpos[g * n + i1] = -1;
    }
}

// ---------------- fused readout (one block per graph) ----------------
__global__ __launch_bounds__(1024) void readout_fused(const float* __restrict__ Hc,
                                                      const float* __restrict__ score,
                                                      const int* __restrict__ oldidx,
                                                      float* __restrict__ accz,
                                                      int k, int first) {
    __shared__ float smax[8][128];
    __shared__ float ssum[8][128];
    int g = blockIdx.x, t = threadIdx.x;
    int f = t & 127, c = t >> 7;   // 8 row-chunks
    float mx = -1e30f, sm = 0.f;
    for (int r = c; r < k; r += 8) {
        int o = oldidx[g * k + r];
        float v = Hc[(size_t)o * H + f] * score[o];
        mx = fmaxf(mx, v);
        sm += v;
    }
    smax[c][f] = mx;
    ssum[c][f] = sm;
    __syncthreads();
    if (c == 0) {
#pragma unroll
        for (int j = 1; j < 8; j++) {
            mx = fmaxf(mx, smax[j][f]);
            sm += ssum[j][f];
        }
        float mean = sm / (float)k;
        if (first) {
            accz[g * 256 + f] = mx;
            accz[g * 256 + 128 + f] = mean;
        } else {
            accz[g * 256 + f] += mx;
            accz[g * 256 + 128 + f] += mean;
        }
    }
}

// ---------------- fused MLP head ----------------
__global__ void mlp_head(const float* __restrict__ accz,
                         const float* __restrict__ lw1, const float* __restrict__ lb1,
                         const float* __restrict__ lw2, const float* __restrict__ lb2,
                         const float* __restrict__ lw3, const float* __restrict__ lb3,
                         float* __restrict__ out) {
    int g = blockIdx.x, j = threadIdx.x;
    __shared__ float z0[256], z1s[128], z2s[64];
    z0[j] = accz[g * 256 + j];
    z0[128 + j] = accz[g * 256 + 128 + j];
    __syncthreads();
    float a = lb1[j];
    for (int q = 0; q < 256; q++) a += z0[q] * lw1[q * 128 + j];
    z1s[j] = fmaxf(a, 0.f);
    __syncthreads();
    if (j < 64) {
        float a2 = lb2[j];
        for (int q = 0; q < 128; q++) a2 += z1s[q] * lw2[q * 64 + j];
        z2s[j] = fmaxf(a2, 0.f);
    }
    __syncthreads();
    if (j < 124) {
        float a3 = lb3[j];
        for (int q = 0; q < 64; q++) a3 += z2s[q] * lw3[q * ACT + j];
        out[g * ACT + j] = 1.f / (1.f + expf(-a3));
    }
}

// ---------------- host orchestration ----------------
extern "C" void kernel_launch(void* const* d_in, const int* in_sizes, int n_in,
                              void* d_out, int out_size) {
    const float* x   = (const float*)d_in[0];
    const int* src   = (const int*)d_in[1];
    const int* dst   = (const int*)d_in[2];
    const float* W1  = (const float*)d_in[3];
    const float* b1  = (const float*)d_in[4];
    const float* W2  = (const float*)d_in[5];
    const float* b2  = (const float*)d_in[6];
    const float* W3  = (const float*)d_in[7];
    const float* b3  = (const float*)d_in[8];
    const float* p1  = (const float*)d_in[9];
    const float* p2  = (const float*)d_in[10];
    const float* p3  = (const float*)d_in[11];
    const float* lw1 = (const float*)d_in[12];
    const float* lb1 = (const float*)d_in[13];
    const float* lw2 = (const float*)d_in[14];
    const float* lb2 = (const float*)d_in[15];
    const float* lw3 = (const float*)d_in[16];
    const float* lb3 = (const float*)d_in[17];
    float* out = (float*)d_out;

    float *buf0, *buf1, *xs, *score, *pnorm, *accz;
    int *cnt, *rowstart, *esrc, *edst, *evalid, *eadj, *newpos, *oldidx, *bsums;
    cudaGetSymbolAddress((void**)&buf0, g_buf0);
    cudaGetSymbolAddress((void**)&buf1, g_buf1);
    cudaGetSymbolAddress((void**)&xs, g_xs);
    cudaGetSymbolAddress((void**)&score, g_score);
    cudaGetSymbolAddress((void**)&pnorm, g_pnorm);
    cudaGetSymbolAddress((void**)&accz, g_accz);
    cudaGetSymbolAddress((void**)&cnt, g_cnt);
    cudaGetSymbolAddress((void**)&rowstart, g_rowstart);
    cudaGetSymbolAddress((void**)&esrc, g_esrc);
    cudaGetSymbolAddress((void**)&edst, g_edst);
    cudaGetSymbolAddress((void**)&evalid, g_evalid);
    cudaGetSymbolAddress((void**)&eadj, g_eadj);
    cudaGetSymbolAddress((void**)&newpos, g_newpos);
    cudaGetSymbolAddress((void**)&oldidx, g_oldidx);
    cudaGetSymbolAddress((void**)&bsums, g_bsums);

    const int npg_[3] = {2048, 1639, 1312};
    const int kk_[3]  = {K1, K2, K3};
    const int nn[4]   = {131072, 64 * K1, 64 * K2, 64 * K3};
    const float* Ws[3] = {W1, W2, W3};
    const float* bs[3] = {b1, b2, b3};
    const float* ps[3] = {p1, p2, p3};

    pnorm_kernel<<<1, 128>>>(p1, p2, p3, pnorm);
    cudaMemsetAsync(cnt, 0, nn[0] * sizeof(int));
    edge_init_count<<<EDG / 256, 256>>>(src, dst, esrc, edst, evalid, cnt);

    for (int l = 0; l < 3; l++) {
        int n = nn[l], k = kk_[l], npg = npg_[l];

        if (l > 0)
            sgemm_pool_tf32<<<(n + 127) / 128, 256>>>(buf1, oldidx, score, cnt, Ws[l], buf0, n);

        int nb = (n + 511) / 512;
        scan_block<<<nb, 512>>>(cnt, rowstart, bsums, n, (l == 0) ? x : nullptr, xs);
        scan_sums_small<<<1, 256>>>(bsums, nb);
        edge_fill<<<EDG / 256, 256>>>(esrc, edst, evalid, rowstart, bsums, eadj);

        if (l == 0)
            gcn_l0_warp<<<(n + 7) / 8, 256>>>(xs, W1, b1, eadj, rowstart, bsums, cnt,
                                              p1, pnorm, buf1, score, n);
        else
            gcn_warp<<<(n + 7) / 8, 256>>>(buf0, eadj, rowstart, bsums, cnt,
                                           bs[l], ps[l], pnorm, l, buf1, score, n);

        topk_radix<<<BGR, 1024>>>(score, npg, k, newpos, oldidx);

        readout_fused<<<BGR, 1024>>>(buf1, score, oldidx, accz, k, (l == 0) ? 1 : 0);

        if (l < 2) {
            cudaMemsetAsync(cnt, 0, nn[l + 1] * sizeof(int));
            remap_count<<<EDG / 256, 256>>>(esrc, edst, evalid, newpos, cnt);
        }
    }

    mlp_head<<<BGR, 128>>>(accz, lw1, lb1, lw2, lb2, lw3, lb3, out);
}